// round 5
// baseline (speedup 1.0000x reference)
#include <cuda_runtime.h>
#include <cuda_bf16.h>
#include <math.h>
#include <stdint.h>

// Problem constants (fixed shapes from setup_inputs)
#define B_   2
#define S_   2048
#define D_   2048
#define H_   16
#define KVH_ 4
#define DH_  128
#define M_   (B_ * S_)          // 4096
#define NQKV 3072               // 2048 q + 512 k + 512 v

// Scratch (static device arrays; no runtime allocation allowed)
__device__ float g_qkv[M_ * NQKV];
__device__ __nv_bfloat16 g_Ahi[M_ * D_];   // residual split; reused as Q hi after rope
__device__ __nv_bfloat16 g_Alo[M_ * D_];
__device__ __nv_bfloat16 g_Whi[NQKV * D_];
__device__ __nv_bfloat16 g_Wlo[NQKV * D_];
__device__ __nv_bfloat16 g_WOhi[D_ * D_];   // transposed: [d][he]
__device__ __nv_bfloat16 g_WOlo[D_ * D_];
__device__ __nv_bfloat16 g_Phi[M_ * D_];    // attention output split
__device__ __nv_bfloat16 g_Plo[M_ * D_];
__device__ __nv_bfloat16 g_Khi[M_ * 512];
__device__ __nv_bfloat16 g_Klo[M_ * 512];
__device__ __nv_bfloat16 g_Vhi[M_ * 512];
__device__ __nv_bfloat16 g_Vlo[M_ * 512];

// ---------------------------------------------------------------------------
// helpers
// ---------------------------------------------------------------------------
__device__ __forceinline__ uint32_t smem_u32(const void* p) {
    uint32_t a;
    asm("{ .reg .u64 t; cvta.to.shared.u64 t, %1; cvt.u32.u64 %0, t; }"
        : "=r"(a) : "l"(p));
    return a;
}

__device__ __forceinline__ void cp16(uint32_t dst, const void* src) {
    asm volatile("cp.async.cg.shared.global [%0], [%1], 16;"
                 :: "r"(dst), "l"(src));
}

__device__ __forceinline__ void ldm_x4(uint32_t* r, uint32_t addr) {
    asm volatile("ldmatrix.sync.aligned.m8n8.x4.shared.b16 {%0,%1,%2,%3}, [%4];"
                 : "=r"(r[0]), "=r"(r[1]), "=r"(r[2]), "=r"(r[3]) : "r"(addr));
}

__device__ __forceinline__ void ldm_x4_t(uint32_t* r, uint32_t addr) {
    asm volatile("ldmatrix.sync.aligned.m8n8.x4.trans.shared.b16 {%0,%1,%2,%3}, [%4];"
                 : "=r"(r[0]), "=r"(r[1]), "=r"(r[2]), "=r"(r[3]) : "r"(addr));
}

__device__ __forceinline__ void mma_bf16(float* c, const uint32_t* a,
                                         uint32_t b0, uint32_t b1) {
    asm volatile(
        "mma.sync.aligned.m16n8k16.row.col.f32.bf16.bf16.f32 "
        "{%0,%1,%2,%3}, {%4,%5,%6,%7}, {%8,%9}, {%0,%1,%2,%3};"
        : "+f"(c[0]), "+f"(c[1]), "+f"(c[2]), "+f"(c[3])
        : "r"(a[0]), "r"(a[1]), "r"(a[2]), "r"(a[3]), "r"(b0), "r"(b1));
}

// swizzled byte offset for a 16B segment (row r, seg s) in a [rows][32]bf16 block
__device__ __forceinline__ uint32_t swz_off(int r, int s) {
    return (uint32_t)(r * 64 + ((s ^ ((r >> 1) & 3)) * 16));
}

// swizzled byte offset for [rows][128 bf16] tiles (256B rows, 16 segs)
__device__ __forceinline__ uint32_t aswz(int r, int sg) {
    return (uint32_t)(r * 256 + ((sg ^ (r & 7)) * 16));
}

__device__ __forceinline__ uint32_t pack_hi2(float x0, float x1, float& r0, float& r1) {
    __nv_bfloat16 h0 = __float2bfloat16(x0);
    __nv_bfloat16 h1 = __float2bfloat16(x1);
    r0 = x0 - __bfloat162float(h0);
    r1 = x1 - __bfloat162float(h1);
    __nv_bfloat162 p = __halves2bfloat162(h0, h1);
    return *(uint32_t*)&p;
}

__device__ __forceinline__ uint32_t pack_bf2(float x0, float x1) {
    __nv_bfloat162 p = __floats2bfloat162_rn(x0, x1);
    return *(uint32_t*)&p;
}

// ---------------------------------------------------------------------------
// HMMA GEMM: C[m,n] = sum_k A[m,k]*B[n,k], fp32 via split-bf16 (hh+hl+lh).
// CTA tile 256x128, 8 warps (4m x 2n), warp tile 64x64. K-chunk 32.
// 3-stage cp.async pipeline; stage = Ah(16K)|Al(16K)|Bh(8K)|Bl(8K) = 48KB.
// ---------------------------------------------------------------------------
#define GEMM_STAGE 49152
#define GEMM_SMEM (3 * GEMM_STAGE)

__global__ __launch_bounds__(256, 1) void hmma_gemm(
    const __nv_bfloat16* __restrict__ Ah, const __nv_bfloat16* __restrict__ Al,
    const __nv_bfloat16* __restrict__ Bh, const __nv_bfloat16* __restrict__ Bl,
    float* __restrict__ C, int ldc)
{
    extern __shared__ char smem[];
    uint32_t sb = smem_u32(smem);

    int tid = threadIdx.x;
    int lane = tid & 31;
    int warp = tid >> 5;
    int warp_m = warp & 3;       // 0..3 (64 rows each)
    int warp_n = warp >> 2;      // 0..1 (64 cols each)
    int m0 = blockIdx.y * 256;
    int n0 = blockIdx.x * 128;

    int q = lane >> 3;
    int lrow = lane & 7;
    int arow_l = (q & 1) * 8 + lrow;
    int ksel = q >> 1;

    float acc[4][8][4];
#pragma unroll
    for (int i = 0; i < 4; i++)
#pragma unroll
        for (int j = 0; j < 8; j++)
#pragma unroll
            for (int k = 0; k < 4; k++) acc[i][j][k] = 0.f;

    auto load_chunk = [&](int c) {
        int k0 = c * 32;
        uint32_t buf = sb + (uint32_t)(c % 3) * GEMM_STAGE;
#pragma unroll
        for (int t = 0; t < 12; t++) {
            int g = tid + t * 256;           // 0..3071
            if (g < 2048) {
                int hl = g >> 10;            // 0 Ah, 1 Al
                int inner = g & 1023;
                int r = inner >> 2, s = inner & 3;
                const void* src = (hl ? Al : Ah)
                    + (size_t)(m0 + r) * 2048 + k0 + s * 8;
                cp16(buf + (uint32_t)hl * 16384u + swz_off(r, s), src);
            } else {
                int g2 = g - 2048;
                int hl = g2 >> 9;            // 0 Bh, 1 Bl
                int inner = g2 & 511;
                int r = inner >> 2, s = inner & 3;
                const void* src = (hl ? Bl : Bh)
                    + (size_t)(n0 + r) * 2048 + k0 + s * 8;
                cp16(buf + 32768u + (uint32_t)hl * 8192u + swz_off(r, s), src);
            }
        }
        asm volatile("cp.async.commit_group;" ::: "memory");
    };

    load_chunk(0);
    load_chunk(1);
    load_chunk(2);

    for (int c = 0; c < 64; c++) {
        asm volatile("cp.async.wait_group 2;" ::: "memory");
        __syncthreads();

        uint32_t buf = sb + (uint32_t)(c % 3) * GEMM_STAGE;
        uint32_t bAh = buf, bAl = buf + 16384, bBh = buf + 32768, bBl = buf + 40960;

#pragma unroll
        for (int ks = 0; ks < 2; ks++) {
            int s = ks * 2 + ksel;
            uint32_t ah[4][4], al[4][4];
#pragma unroll
            for (int mi = 0; mi < 4; mi++) {
                int r = warp_m * 64 + mi * 16 + arow_l;
                ldm_x4(ah[mi], bAh + swz_off(r, s));
                ldm_x4(al[mi], bAl + swz_off(r, s));
            }
            uint32_t bh[8][2], bl[8][2];
#pragma unroll
            for (int j = 0; j < 4; j++) {
                int r = warp_n * 64 + j * 16 + arow_l;
                uint32_t t4[4];
                ldm_x4(t4, bBh + swz_off(r, s));
                bh[j * 2 + 0][0] = t4[0]; bh[j * 2 + 0][1] = t4[2];
                bh[j * 2 + 1][0] = t4[1]; bh[j * 2 + 1][1] = t4[3];
                ldm_x4(t4, bBl + swz_off(r, s));
                bl[j * 2 + 0][0] = t4[0]; bl[j * 2 + 0][1] = t4[2];
                bl[j * 2 + 1][0] = t4[1]; bl[j * 2 + 1][1] = t4[3];
            }
#pragma unroll
            for (int mi = 0; mi < 4; mi++) {
#pragma unroll
                for (int nj = 0; nj < 8; nj++) {
                    mma_bf16(acc[mi][nj], ah[mi], bh[nj][0], bh[nj][1]);
                    mma_bf16(acc[mi][nj], ah[mi], bl[nj][0], bl[nj][1]);
                    mma_bf16(acc[mi][nj], al[mi], bh[nj][0], bh[nj][1]);
                }
            }
        }
        __syncthreads();
        if (c + 3 < 64) load_chunk(c + 3);
        else asm volatile("cp.async.commit_group;" ::: "memory");  // keep count
    }

    int rr = lane >> 2;
    int cc = (lane & 3) * 2;
#pragma unroll
    for (int mi = 0; mi < 4; mi++) {
        int r1 = m0 + warp_m * 64 + mi * 16 + rr;
#pragma unroll
        for (int nj = 0; nj < 8; nj++) {
            int col = n0 + warp_n * 64 + nj * 8 + cc;
            float2 v0 = make_float2(acc[mi][nj][0], acc[mi][nj][1]);
            float2 v1 = make_float2(acc[mi][nj][2], acc[mi][nj][3]);
            *(float2*)&C[(size_t)r1 * ldc + col] = v0;
            *(float2*)&C[(size_t)(r1 + 8) * ldc + col] = v1;
        }
    }
}

// ---------------------------------------------------------------------------
// Elementwise fp32 -> (bf16 hi, bf16 lo) split
// ---------------------------------------------------------------------------
__global__ __launch_bounds__(256) void split_kernel(
    const float* __restrict__ src, __nv_bfloat16* __restrict__ hi,
    __nv_bfloat16* __restrict__ lo, int n4)
{
    int i = blockIdx.x * 256 + threadIdx.x;
    if (i >= n4) return;
    float4 v = ((const float4*)src)[i];
    __nv_bfloat16 h0 = __float2bfloat16(v.x);
    __nv_bfloat16 h1 = __float2bfloat16(v.y);
    __nv_bfloat16 h2 = __float2bfloat16(v.z);
    __nv_bfloat16 h3 = __float2bfloat16(v.w);
    __nv_bfloat16 l0 = __float2bfloat16(v.x - __bfloat162float(h0));
    __nv_bfloat16 l1 = __float2bfloat16(v.y - __bfloat162float(h1));
    __nv_bfloat16 l2 = __float2bfloat16(v.z - __bfloat162float(h2));
    __nv_bfloat16 l3 = __float2bfloat16(v.w - __bfloat162float(h3));
    ushort4 hv = make_ushort4(__bfloat16_as_ushort(h0), __bfloat16_as_ushort(h1),
                              __bfloat16_as_ushort(h2), __bfloat16_as_ushort(h3));
    ushort4 lv = make_ushort4(__bfloat16_as_ushort(l0), __bfloat16_as_ushort(l1),
                              __bfloat16_as_ushort(l2), __bfloat16_as_ushort(l3));
    ((ushort4*)hi)[i] = hv;
    ((ushort4*)lo)[i] = lv;
}

// ---------------------------------------------------------------------------
// Transpose + split W_O: in [he=2048][d=2048] -> out [d][he] hi/lo bf16
// ---------------------------------------------------------------------------
__global__ __launch_bounds__(256) void transpose_split_wo(
    const float* __restrict__ W, __nv_bfloat16* __restrict__ Th,
    __nv_bfloat16* __restrict__ Tl)
{
    __shared__ float t[32][33];
    int bx = blockIdx.x * 32;
    int by = blockIdx.y * 32;
    int x = threadIdx.x & 31;
    int y0 = threadIdx.x >> 5;
#pragma unroll
    for (int i = 0; i < 32; i += 8)
        t[y0 + i][x] = W[(size_t)(by + y0 + i) * 2048 + bx + x];
    __syncthreads();
#pragma unroll
    for (int i = 0; i < 32; i += 8) {
        float v = t[x][y0 + i];
        __nv_bfloat16 h = __float2bfloat16(v);
        __nv_bfloat16 l = __float2bfloat16(v - __bfloat162float(h));
        size_t o = (size_t)(bx + y0 + i) * 2048 + by + x;
        Th[o] = h;
        Tl[o] = l;
    }
}

// ---------------------------------------------------------------------------
// RoPE + precision-split producer
// ---------------------------------------------------------------------------
__global__ __launch_bounds__(256) void rope_split_kernel(
    const float* __restrict__ qkv,
    float* __restrict__ kc, float* __restrict__ vc,
    __nv_bfloat16* __restrict__ Qhi, __nv_bfloat16* __restrict__ Qlo,
    __nv_bfloat16* __restrict__ Khi, __nv_bfloat16* __restrict__ Klo,
    __nv_bfloat16* __restrict__ Vhi, __nv_bfloat16* __restrict__ Vlo,
    const int* __restrict__ sp_ptr)
{
    const float LOG2_BASE_OVER_HALF = 13.287712379549449f / 64.0f;
    const float scale = 0.08838834764831845f;  // 1/sqrt(128)
    int m = blockIdx.x;
    int s = m & (S_ - 1);
    int sp = *sp_ptr;
    float pos = (float)(sp + s);
    int tid = threadIdx.x;

    for (int p = tid; p < H_ * 64; p += 256) {
        int h = p >> 6, e = p & 63;
        float inv = exp2f(-(float)e * LOG2_BASE_OVER_HALF);
        float ang = pos * inv;
        float sn, cs;
        sincosf(ang, &sn, &cs);
        const float* base = qkv + (size_t)m * NQKV + h * DH_;
        float x1 = base[e], x2 = base[e + 64];
        float y1 = (x1 * cs - x2 * sn) * scale;
        float y2 = (x1 * sn + x2 * cs) * scale;
        size_t o = (size_t)m * D_ + h * DH_;
        __nv_bfloat16 h1 = __float2bfloat16(y1);
        __nv_bfloat16 h2 = __float2bfloat16(y2);
        Qhi[o + e]      = h1;
        Qhi[o + e + 64] = h2;
        Qlo[o + e]      = __float2bfloat16(y1 - __bfloat162float(h1));
        Qlo[o + e + 64] = __float2bfloat16(y2 - __bfloat162float(h2));
    }
    for (int p = tid; p < KVH_ * 64; p += 256) {
        int h = p >> 6, e = p & 63;
        float inv = exp2f(-(float)e * LOG2_BASE_OVER_HALF);
        float ang = pos * inv;
        float sn, cs;
        sincosf(ang, &sn, &cs);
        const float* base = qkv + (size_t)m * NQKV + 2048 + h * DH_;
        float x1 = base[e], x2 = base[e + 64];
        float y1 = x1 * cs - x2 * sn;
        float y2 = x1 * sn + x2 * cs;
        size_t o = (size_t)m * (KVH_ * DH_) + h * DH_;
        kc[o + e]      = y1;
        kc[o + e + 64] = y2;
        __nv_bfloat16 h1 = __float2bfloat16(y1);
        __nv_bfloat16 h2 = __float2bfloat16(y2);
        Khi[o + e]      = h1;
        Khi[o + e + 64] = h2;
        Klo[o + e]      = __float2bfloat16(y1 - __bfloat162float(h1));
        Klo[o + e + 64] = __float2bfloat16(y2 - __bfloat162float(h2));
    }
    for (int i = tid; i < KVH_ * DH_; i += 256) {
        float v = qkv[(size_t)m * NQKV + 2560 + i];
        size_t o = (size_t)m * (KVH_ * DH_) + i;
        vc[o] = v;
        __nv_bfloat16 h = __float2bfloat16(v);
        Vhi[o] = h;
        Vlo[o] = __float2bfloat16(v - __bfloat162float(h));
    }
}

// ---------------------------------------------------------------------------
// Tensor-core flash attention, split-bf16 numerics.
// BM=128 (8 warps, m16 each), BN=64, Dh=128, double-buffered K/V.
// smem: Q hi/lo 64KB + 2 KV stages x 64KB = 192KB, 1 CTA/SM.
// ---------------------------------------------------------------------------
#define ATT_KV_STAGE 65536
#define ATT2_SMEM (65536 + 2 * ATT_KV_STAGE)

__global__ __launch_bounds__(256, 1) void attn_mma_kernel(
    const __nv_bfloat16* __restrict__ Qhi, const __nv_bfloat16* __restrict__ Qlo,
    const __nv_bfloat16* __restrict__ Khi, const __nv_bfloat16* __restrict__ Klo,
    const __nv_bfloat16* __restrict__ Vhi, const __nv_bfloat16* __restrict__ Vlo,
    __nv_bfloat16* __restrict__ Ohi, __nv_bfloat16* __restrict__ Olo,
    const int* __restrict__ sp_ptr)
{
    extern __shared__ char smem[];
    uint32_t sb = smem_u32(smem);
    const uint32_t sQh = sb, sQl = sb + 32768;
    const uint32_t sKV = sb + 65536;    // stage base

    int tid = threadIdx.x;
    int lane = tid & 31;
    int warp = tid >> 5;                 // 0..7
    int bh = blockIdx.y;
    int b = bh >> 4, h = bh & 15, kvh = h >> 2;
    int q0 = blockIdx.x * 128;
    int sp = *sp_ptr;
    float slope = exp2f(-0.5f * (float)(h + 1));

    int fr = ((lane >> 3) & 1) * 8 + (lane & 7);
    int fs = lane >> 4;

    int kt_end = (sp + q0 + 127) >> 6;
    if (kt_end > S_ / 64 - 1) kt_end = S_ / 64 - 1;

    // ---- KV tile loader ----
    auto load_kv = [&](int kt) {
        int k0 = kt * 64;
        uint32_t stage = sKV + (uint32_t)(kt & 1) * ATT_KV_STAGE;
#pragma unroll
        for (int i = 0; i < 16; i++) {
            int idx = tid + i * 256;   // 0..4095
            int t = idx >> 10;         // 0 Khi 1 Klo 2 Vhi 3 Vlo
            int inner = idx & 1023;
            int r = inner >> 4, sg = inner & 15;
            const __nv_bfloat16* basep =
                (t == 0) ? Khi : (t == 1) ? Klo : (t == 2) ? Vhi : Vlo;
            const __nv_bfloat16* src =
                basep + (size_t)(b * S_ + k0 + r) * 512 + kvh * 128 + sg * 8;
            cp16(stage + (uint32_t)t * 16384u + aswz(r, sg), src);
        }
    };

    // ---- prologue: Q + KV(0) as group 0, KV(1) as group 1 ----
#pragma unroll
    for (int i = 0; i < 16; i++) {
        int idx = tid + i * 256;          // 0..4095
        int t = idx >> 11;                // 0 hi, 1 lo
        int inner = idx & 2047;
        int r = inner >> 4, sg = inner & 15;
        const __nv_bfloat16* src = (t ? Qlo : Qhi)
            + (size_t)(b * S_ + q0 + r) * 2048 + h * 128 + sg * 8;
        cp16((t ? sQl : sQh) + aswz(r, sg), src);
    }
    load_kv(0);
    asm volatile("cp.async.commit_group;" ::: "memory");
    load_kv(1);   // kt_end >= 1 always (q0 >= 0, BM=128)
    asm volatile("cp.async.commit_group;" ::: "memory");

    float Oacc[16][4];
#pragma unroll
    for (int e = 0; e < 16; e++)
#pragma unroll
        for (int k = 0; k < 4; k++) Oacc[e][k] = 0.f;
    float m0r = -1e30f, m1r = -1e30f;
    float l0r = 0.f, l1r = 0.f;

    int row0 = q0 + warp * 16 + (lane >> 2);
    int qp0 = sp + row0, qp1 = qp0 + 8;

    for (int kt = 0; kt <= kt_end; kt++) {
        int k0 = kt * 64;
        asm volatile("cp.async.wait_group 1;" ::: "memory");
        __syncthreads();

        uint32_t stage = sKV + (uint32_t)(kt & 1) * ATT_KV_STAGE;
        uint32_t sKh = stage, sKl = stage + 16384;
        uint32_t sVh = stage + 32768, sVl = stage + 49152;

        // ---- S = Q K^T (split: hh + hl + lh) ----
        float sacc[8][4];
#pragma unroll
        for (int nj = 0; nj < 8; nj++)
#pragma unroll
            for (int k = 0; k < 4; k++) sacc[nj][k] = 0.f;

#pragma unroll
        for (int s = 0; s < 8; s++) {
            uint32_t qh[4], ql[4], t4[4];
            ldm_x4(qh, sQh + aswz(warp * 16 + fr, 2 * s + fs));
            ldm_x4(ql, sQl + aswz(warp * 16 + fr, 2 * s + fs));
            uint32_t kbh[8][2], kbl[8][2];
#pragma unroll
            for (int j = 0; j < 4; j++) {
                ldm_x4(t4, sKh + aswz(j * 16 + fr, 2 * s + fs));
                kbh[2 * j][0] = t4[0]; kbh[2 * j][1] = t4[2];
                kbh[2 * j + 1][0] = t4[1]; kbh[2 * j + 1][1] = t4[3];
                ldm_x4(t4, sKl + aswz(j * 16 + fr, 2 * s + fs));
                kbl[2 * j][0] = t4[0]; kbl[2 * j][1] = t4[2];
                kbl[2 * j + 1][0] = t4[1]; kbl[2 * j + 1][1] = t4[3];
            }
#pragma unroll
            for (int nj = 0; nj < 8; nj++) {
                mma_bf16(sacc[nj], qh, kbh[nj][0], kbh[nj][1]);
                mma_bf16(sacc[nj], qh, kbl[nj][0], kbl[nj][1]);
                mma_bf16(sacc[nj], ql, kbh[nj][0], kbh[nj][1]);
            }
        }

        // ---- bias + causal mask ----
#pragma unroll
        for (int nj = 0; nj < 8; nj++) {
            int c = k0 + nj * 8 + (lane & 3) * 2;
            sacc[nj][0] = (c     <= qp0) ? sacc[nj][0] - slope * (float)(qp0 - c)     : -1e30f;
            sacc[nj][1] = (c + 1 <= qp0) ? sacc[nj][1] - slope * (float)(qp0 - c - 1) : -1e30f;
            sacc[nj][2] = (c     <= qp1) ? sacc[nj][2] - slope * (float)(qp1 - c)     : -1e30f;
            sacc[nj][3] = (c + 1 <= qp1) ? sacc[nj][3] - slope * (float)(qp1 - c - 1) : -1e30f;
        }

        // ---- online softmax ----
        float mx0 = -1e30f, mx1 = -1e30f;
#pragma unroll
        for (int nj = 0; nj < 8; nj++) {
            mx0 = fmaxf(mx0, fmaxf(sacc[nj][0], sacc[nj][1]));
            mx1 = fmaxf(mx1, fmaxf(sacc[nj][2], sacc[nj][3]));
        }
        mx0 = fmaxf(mx0, __shfl_xor_sync(0xffffffffu, mx0, 1));
        mx0 = fmaxf(mx0, __shfl_xor_sync(0xffffffffu, mx0, 2));
        mx1 = fmaxf(mx1, __shfl_xor_sync(0xffffffffu, mx1, 1));
        mx1 = fmaxf(mx1, __shfl_xor_sync(0xffffffffu, mx1, 2));
        float mn0 = fmaxf(m0r, mx0), mn1 = fmaxf(m1r, mx1);
        float corr0 = __expf(m0r - mn0), corr1 = __expf(m1r - mn1);
        m0r = mn0; m1r = mn1;

        float ls0 = 0.f, ls1 = 0.f;
#pragma unroll
        for (int nj = 0; nj < 8; nj++) {
            sacc[nj][0] = __expf(sacc[nj][0] - mn0);
            sacc[nj][1] = __expf(sacc[nj][1] - mn0);
            sacc[nj][2] = __expf(sacc[nj][2] - mn1);
            sacc[nj][3] = __expf(sacc[nj][3] - mn1);
            ls0 += sacc[nj][0] + sacc[nj][1];
            ls1 += sacc[nj][2] + sacc[nj][3];
        }
        ls0 += __shfl_xor_sync(0xffffffffu, ls0, 1);
        ls0 += __shfl_xor_sync(0xffffffffu, ls0, 2);
        ls1 += __shfl_xor_sync(0xffffffffu, ls1, 1);
        ls1 += __shfl_xor_sync(0xffffffffu, ls1, 2);
        l0r = l0r * corr0 + ls0;
        l1r = l1r * corr1 + ls1;

#pragma unroll
        for (int e = 0; e < 16; e++) {
            Oacc[e][0] *= corr0; Oacc[e][1] *= corr0;
            Oacc[e][2] *= corr1; Oacc[e][3] *= corr1;
        }

        // ---- P -> bf16 hi/lo A-fragments ----
        uint32_t phi[4][4], plo[4][4];
#pragma unroll
        for (int t = 0; t < 4; t++) {
            float r0, r1;
            phi[t][0] = pack_hi2(sacc[2 * t][0], sacc[2 * t][1], r0, r1);
            plo[t][0] = pack_bf2(r0, r1);
            phi[t][1] = pack_hi2(sacc[2 * t][2], sacc[2 * t][3], r0, r1);
            plo[t][1] = pack_bf2(r0, r1);
            phi[t][2] = pack_hi2(sacc[2 * t + 1][0], sacc[2 * t + 1][1], r0, r1);
            plo[t][2] = pack_bf2(r0, r1);
            phi[t][3] = pack_hi2(sacc[2 * t + 1][2], sacc[2 * t + 1][3], r0, r1);
            plo[t][3] = pack_bf2(r0, r1);
        }

        // ---- O += P V (split: hh + hl + lh) ----
#pragma unroll
        for (int t = 0; t < 4; t++) {
#pragma unroll
            for (int u = 0; u < 8; u++) {
                uint32_t th[4], tl[4];
                ldm_x4_t(th, sVh + aswz(t * 16 + fr, 2 * u + fs));
                ldm_x4_t(tl, sVl + aswz(t * 16 + fr, 2 * u + fs));
                mma_bf16(Oacc[2 * u], phi[t], th[0], th[1]);
                mma_bf16(Oacc[2 * u], phi[t], tl[0], tl[1]);
                mma_bf16(Oacc[2 * u], plo[t], th[0], th[1]);
                mma_bf16(Oacc[2 * u + 1], phi[t], th[2], th[3]);
                mma_bf16(Oacc[2 * u + 1], phi[t], tl[2], tl[3]);
                mma_bf16(Oacc[2 * u + 1], plo[t], th[2], th[3]);
            }
        }
        __syncthreads();
        if (kt + 2 <= kt_end) load_kv(kt + 2);
        asm volatile("cp.async.commit_group;" ::: "memory");
    }

    // ---- epilogue: normalize + split to bf16 hi/lo ----
    float inv0 = 1.f / l0r, inv1 = 1.f / l1r;
    size_t row0g = (size_t)(b * S_ + row0);
#pragma unroll
    for (int e = 0; e < 16; e++) {
        int colb = h * 128 + e * 8 + (lane & 3) * 2;
        float x0 = Oacc[e][0] * inv0, x1 = Oacc[e][1] * inv0;
        float x2 = Oacc[e][2] * inv1, x3 = Oacc[e][3] * inv1;
        float r0, r1;
        uint32_t hp0 = pack_hi2(x0, x1, r0, r1);
        uint32_t lp0 = pack_bf2(r0, r1);
        uint32_t hp1 = pack_hi2(x2, x3, r0, r1);
        uint32_t lp1 = pack_bf2(r0, r1);
        *(uint32_t*)&Ohi[row0g * 2048 + colb] = hp0;
        *(uint32_t*)&Olo[row0g * 2048 + colb] = lp0;
        *(uint32_t*)&Ohi[(row0g + 8) * 2048 + colb] = hp1;
        *(uint32_t*)&Olo[(row0g + 8) * 2048 + colb] = lp1;
    }
}

// ---------------------------------------------------------------------------
extern "C" void kernel_launch(void* const* d_in, const int* in_sizes, int n_in,
                              void* d_out, int out_size)
{
    const float* residual = (const float*)d_in[0];
    const float* W_Q = (const float*)d_in[1];
    const float* W_K = (const float*)d_in[2];
    const float* W_V = (const float*)d_in[3];
    const float* W_O = (const float*)d_in[4];
    const int* sp = (const int*)d_in[5];

    float* out = (float*)d_out;
    float* k_cache = out + (size_t)B_ * S_ * D_;
    float* v_cache = k_cache + (size_t)B_ * S_ * KVH_ * DH_;

    float* qkv_ptr;
    __nv_bfloat16 *Ahi, *Alo, *Whi, *Wlo, *WOhi, *WOlo, *Phi, *Plo;
    __nv_bfloat16 *Khi, *Klo, *Vhi, *Vlo;
    cudaGetSymbolAddress((void**)&qkv_ptr, g_qkv);
    cudaGetSymbolAddress((void**)&Ahi, g_Ahi);
    cudaGetSymbolAddress((void**)&Alo, g_Alo);
    cudaGetSymbolAddress((void**)&Whi, g_Whi);
    cudaGetSymbolAddress((void**)&Wlo, g_Wlo);
    cudaGetSymbolAddress((void**)&WOhi, g_WOhi);
    cudaGetSymbolAddress((void**)&WOlo, g_WOlo);
    cudaGetSymbolAddress((void**)&Phi, g_Phi);
    cudaGetSymbolAddress((void**)&Plo, g_Plo);
    cudaGetSymbolAddress((void**)&Khi, g_Khi);
    cudaGetSymbolAddress((void**)&Klo, g_Klo);
    cudaGetSymbolAddress((void**)&Vhi, g_Vhi);
    cudaGetSymbolAddress((void**)&Vlo, g_Vlo);

    cudaFuncSetAttribute(hmma_gemm, cudaFuncAttributeMaxDynamicSharedMemorySize,
                         GEMM_SMEM);
    cudaFuncSetAttribute(attn_mma_kernel, cudaFuncAttributeMaxDynamicSharedMemorySize,
                         ATT2_SMEM);

    // 0) splits
    split_kernel<<<(M_ * D_ / 4 + 255) / 256, 256>>>(residual, Ahi, Alo, M_ * D_ / 4);
    split_kernel<<<(2048 * 2048 / 4 + 255) / 256, 256>>>(W_Q, Whi, Wlo, 2048 * 2048 / 4);
    split_kernel<<<(512 * 2048 / 4 + 255) / 256, 256>>>(
        W_K, Whi + (size_t)2048 * 2048, Wlo + (size_t)2048 * 2048, 512 * 2048 / 4);
    split_kernel<<<(512 * 2048 / 4 + 255) / 256, 256>>>(
        W_V, Whi + (size_t)2560 * 2048, Wlo + (size_t)2560 * 2048, 512 * 2048 / 4);
    transpose_split_wo<<<dim3(64, 64), 256>>>(W_O, WOhi, WOlo);

    // 1) fused QKV projection
    hmma_gemm<<<dim3(NQKV / 128, M_ / 256), 256, GEMM_SMEM>>>(
        Ahi, Alo, Whi, Wlo, qkv_ptr, NQKV);

    // 2) RoPE + split producer (reuses Ahi/Alo as Qhi/Qlo)
    rope_split_kernel<<<M_, 256>>>(qkv_ptr, k_cache, v_cache,
                                   Ahi, Alo, Khi, Klo, Vhi, Vlo, sp);

    // 3) tensor-core attention -> bf16 hi/lo output (Phi/Plo)
    attn_mma_kernel<<<dim3(S_ / 128, B_ * H_), 256, ATT2_SMEM>>>(
        Ahi, Alo, Khi, Klo, Vhi, Vlo, Phi, Plo, sp);

    // 4) output projection
    hmma_gemm<<<dim3(D_ / 128, M_ / 256), 256, GEMM_SMEM>>>(
        Phi, Plo, WOhi, WOlo, out, D_);
}

// round 6
// speedup vs baseline: 1.0359x; 1.0359x over previous
#include <cuda_runtime.h>
#include <cuda_bf16.h>
#include <math.h>
#include <stdint.h>

// Problem constants (fixed shapes from setup_inputs)
#define B_   2
#define S_   2048
#define D_   2048
#define H_   16
#define KVH_ 4
#define DH_  128
#define M_   (B_ * S_)          // 4096
#define NQKV 3072               // 2048 q + 512 k + 512 v

// Scratch (static device arrays; no runtime allocation allowed)
__device__ float g_qkv[M_ * NQKV];
__device__ __nv_bfloat16 g_Ahi[M_ * D_];   // residual split; reused as Q hi after rope
__device__ __nv_bfloat16 g_Alo[M_ * D_];
__device__ __nv_bfloat16 g_Whi[NQKV * D_];
__device__ __nv_bfloat16 g_Wlo[NQKV * D_];
__device__ __nv_bfloat16 g_WOhi[D_ * D_];   // transposed: [d][he]
__device__ __nv_bfloat16 g_WOlo[D_ * D_];
__device__ __nv_bfloat16 g_Phi[M_ * D_];    // attention output split
__device__ __nv_bfloat16 g_Plo[M_ * D_];
__device__ __nv_bfloat16 g_Khi[M_ * 512];
__device__ __nv_bfloat16 g_Klo[M_ * 512];
__device__ __nv_bfloat16 g_Vhi[M_ * 512];
__device__ __nv_bfloat16 g_Vlo[M_ * 512];

// ---------------------------------------------------------------------------
// helpers
// ---------------------------------------------------------------------------
__device__ __forceinline__ uint32_t smem_u32(const void* p) {
    uint32_t a;
    asm("{ .reg .u64 t; cvta.to.shared.u64 t, %1; cvt.u32.u64 %0, t; }"
        : "=r"(a) : "l"(p));
    return a;
}

__device__ __forceinline__ void cp16(uint32_t dst, const void* src) {
    asm volatile("cp.async.cg.shared.global [%0], [%1], 16;"
                 :: "r"(dst), "l"(src));
}

__device__ __forceinline__ void ldm_x4(uint32_t* r, uint32_t addr) {
    asm volatile("ldmatrix.sync.aligned.m8n8.x4.shared.b16 {%0,%1,%2,%3}, [%4];"
                 : "=r"(r[0]), "=r"(r[1]), "=r"(r[2]), "=r"(r[3]) : "r"(addr));
}

__device__ __forceinline__ void ldm_x4_t(uint32_t* r, uint32_t addr) {
    asm volatile("ldmatrix.sync.aligned.m8n8.x4.trans.shared.b16 {%0,%1,%2,%3}, [%4];"
                 : "=r"(r[0]), "=r"(r[1]), "=r"(r[2]), "=r"(r[3]) : "r"(addr));
}

__device__ __forceinline__ void mma_bf16(float* c, const uint32_t* a,
                                         uint32_t b0, uint32_t b1) {
    asm volatile(
        "mma.sync.aligned.m16n8k16.row.col.f32.bf16.bf16.f32 "
        "{%0,%1,%2,%3}, {%4,%5,%6,%7}, {%8,%9}, {%0,%1,%2,%3};"
        : "+f"(c[0]), "+f"(c[1]), "+f"(c[2]), "+f"(c[3])
        : "r"(a[0]), "r"(a[1]), "r"(a[2]), "r"(a[3]), "r"(b0), "r"(b1));
}

// swizzled byte offset for a 16B segment (row r, seg s) in a [rows][32]bf16 block
__device__ __forceinline__ uint32_t swz_off(int r, int s) {
    return (uint32_t)(r * 64 + ((s ^ ((r >> 1) & 3)) * 16));
}

// swizzled byte offset for [rows][128 bf16] tiles (256B rows, 16 segs)
__device__ __forceinline__ uint32_t aswz(int r, int sg) {
    return (uint32_t)(r * 256 + ((sg ^ (r & 7)) * 16));
}

__device__ __forceinline__ uint32_t pack_hi2(float x0, float x1, float& r0, float& r1) {
    __nv_bfloat16 h0 = __float2bfloat16(x0);
    __nv_bfloat16 h1 = __float2bfloat16(x1);
    r0 = x0 - __bfloat162float(h0);
    r1 = x1 - __bfloat162float(h1);
    __nv_bfloat162 p = __halves2bfloat162(h0, h1);
    return *(uint32_t*)&p;
}

__device__ __forceinline__ uint32_t pack_bf2(float x0, float x1) {
    __nv_bfloat162 p = __floats2bfloat162_rn(x0, x1);
    return *(uint32_t*)&p;
}

// ---------------------------------------------------------------------------
// HMMA GEMM (R4 tile shape + 3-stage pipeline, 2 CTAs/SM):
// C[m,n] = sum_k A[m,k]*B[n,k], fp32 via split-bf16 (hh+hl+lh).
// CTA tile 128x128, 8 warps (4m x 2n), warp tile 32x64. K-chunk 32.
// stage = Ah|Al|Bh|Bl, each [128][32]bf16 (8KB) = 32KB; 3 stages = 96KB.
// ---------------------------------------------------------------------------
#define GEMM_STAGE 32768
#define GEMM_SMEM (3 * GEMM_STAGE)

__global__ __launch_bounds__(256, 2) void hmma_gemm(
    const __nv_bfloat16* __restrict__ Ah, const __nv_bfloat16* __restrict__ Al,
    const __nv_bfloat16* __restrict__ Bh, const __nv_bfloat16* __restrict__ Bl,
    float* __restrict__ C, int ldc)
{
    extern __shared__ char smem[];
    uint32_t sb = smem_u32(smem);

    int tid = threadIdx.x;
    int lane = tid & 31;
    int warp = tid >> 5;
    int warp_m = warp & 3;
    int warp_n = warp >> 2;
    int m0 = blockIdx.y * 128;
    int n0 = blockIdx.x * 128;

    int q = lane >> 3;
    int lrow = lane & 7;
    int arow_l = (q & 1) * 8 + lrow;
    int ksel = q >> 1;

    float acc[2][8][4];
#pragma unroll
    for (int i = 0; i < 2; i++)
#pragma unroll
        for (int j = 0; j < 8; j++)
#pragma unroll
            for (int k = 0; k < 4; k++) acc[i][j][k] = 0.f;

    auto load_chunk = [&](int c) {
        int k0 = c * 32;
        uint32_t buf = sb + (uint32_t)(c % 3) * GEMM_STAGE;
#pragma unroll
        for (int t = 0; t < 8; t++) {
            int g = tid + t * 256;
            int mat = g >> 9;
            int inner = g & 511;
            int r = inner >> 2;
            int s = inner & 3;
            const __nv_bfloat16* base =
                (mat == 0) ? Ah : (mat == 1) ? Al : (mat == 2) ? Bh : Bl;
            int row = ((mat < 2) ? m0 : n0) + r;
            const void* src = base + (size_t)row * 2048 + k0 + s * 8;
            cp16(buf + (uint32_t)mat * 8192u + swz_off(r, s), src);
        }
        asm volatile("cp.async.commit_group;" ::: "memory");
    };

    load_chunk(0);
    load_chunk(1);
    load_chunk(2);

    for (int c = 0; c < 64; c++) {
        asm volatile("cp.async.wait_group 2;" ::: "memory");
        __syncthreads();

        uint32_t buf = sb + (uint32_t)(c % 3) * GEMM_STAGE;
        uint32_t bAh = buf, bAl = buf + 8192, bBh = buf + 16384, bBl = buf + 24576;

#pragma unroll
        for (int ks = 0; ks < 2; ks++) {
            int s = ks * 2 + ksel;
            uint32_t ah[2][4], al[2][4];
#pragma unroll
            for (int mi = 0; mi < 2; mi++) {
                int r = warp_m * 32 + mi * 16 + arow_l;
                ldm_x4(ah[mi], bAh + swz_off(r, s));
                ldm_x4(al[mi], bAl + swz_off(r, s));
            }
            uint32_t bh[8][2], bl[8][2];
#pragma unroll
            for (int j = 0; j < 4; j++) {
                int r = warp_n * 64 + j * 16 + arow_l;
                uint32_t t4[4];
                ldm_x4(t4, bBh + swz_off(r, s));
                bh[j * 2 + 0][0] = t4[0]; bh[j * 2 + 0][1] = t4[2];
                bh[j * 2 + 1][0] = t4[1]; bh[j * 2 + 1][1] = t4[3];
                ldm_x4(t4, bBl + swz_off(r, s));
                bl[j * 2 + 0][0] = t4[0]; bl[j * 2 + 0][1] = t4[2];
                bl[j * 2 + 1][0] = t4[1]; bl[j * 2 + 1][1] = t4[3];
            }
#pragma unroll
            for (int mi = 0; mi < 2; mi++) {
#pragma unroll
                for (int nj = 0; nj < 8; nj++) {
                    mma_bf16(acc[mi][nj], ah[mi], bh[nj][0], bh[nj][1]);
                    mma_bf16(acc[mi][nj], ah[mi], bl[nj][0], bl[nj][1]);
                    mma_bf16(acc[mi][nj], al[mi], bh[nj][0], bh[nj][1]);
                }
            }
        }
        __syncthreads();
        if (c + 3 < 64) load_chunk(c + 3);
        else asm volatile("cp.async.commit_group;" ::: "memory");
    }

    int rr = lane >> 2;
    int cc = (lane & 3) * 2;
#pragma unroll
    for (int mi = 0; mi < 2; mi++) {
        int r1 = m0 + warp_m * 32 + mi * 16 + rr;
#pragma unroll
        for (int nj = 0; nj < 8; nj++) {
            int col = n0 + warp_n * 64 + nj * 8 + cc;
            float2 v0 = make_float2(acc[mi][nj][0], acc[mi][nj][1]);
            float2 v1 = make_float2(acc[mi][nj][2], acc[mi][nj][3]);
            *(float2*)&C[(size_t)r1 * ldc + col] = v0;
            *(float2*)&C[(size_t)(r1 + 8) * ldc + col] = v1;
        }
    }
}

// ---------------------------------------------------------------------------
// Elementwise fp32 -> (bf16 hi, bf16 lo) split
// ---------------------------------------------------------------------------
__global__ __launch_bounds__(256) void split_kernel(
    const float* __restrict__ src, __nv_bfloat16* __restrict__ hi,
    __nv_bfloat16* __restrict__ lo, int n4)
{
    int i = blockIdx.x * 256 + threadIdx.x;
    if (i >= n4) return;
    float4 v = ((const float4*)src)[i];
    __nv_bfloat16 h0 = __float2bfloat16(v.x);
    __nv_bfloat16 h1 = __float2bfloat16(v.y);
    __nv_bfloat16 h2 = __float2bfloat16(v.z);
    __nv_bfloat16 h3 = __float2bfloat16(v.w);
    __nv_bfloat16 l0 = __float2bfloat16(v.x - __bfloat162float(h0));
    __nv_bfloat16 l1 = __float2bfloat16(v.y - __bfloat162float(h1));
    __nv_bfloat16 l2 = __float2bfloat16(v.z - __bfloat162float(h2));
    __nv_bfloat16 l3 = __float2bfloat16(v.w - __bfloat162float(h3));
    ushort4 hv = make_ushort4(__bfloat16_as_ushort(h0), __bfloat16_as_ushort(h1),
                              __bfloat16_as_ushort(h2), __bfloat16_as_ushort(h3));
    ushort4 lv = make_ushort4(__bfloat16_as_ushort(l0), __bfloat16_as_ushort(l1),
                              __bfloat16_as_ushort(l2), __bfloat16_as_ushort(l3));
    ((ushort4*)hi)[i] = hv;
    ((ushort4*)lo)[i] = lv;
}

// ---------------------------------------------------------------------------
// Transpose + split W_O: in [he=2048][d=2048] -> out [d][he] hi/lo bf16
// ---------------------------------------------------------------------------
__global__ __launch_bounds__(256) void transpose_split_wo(
    const float* __restrict__ W, __nv_bfloat16* __restrict__ Th,
    __nv_bfloat16* __restrict__ Tl)
{
    __shared__ float t[32][33];
    int bx = blockIdx.x * 32;
    int by = blockIdx.y * 32;
    int x = threadIdx.x & 31;
    int y0 = threadIdx.x >> 5;
#pragma unroll
    for (int i = 0; i < 32; i += 8)
        t[y0 + i][x] = W[(size_t)(by + y0 + i) * 2048 + bx + x];
    __syncthreads();
#pragma unroll
    for (int i = 0; i < 32; i += 8) {
        float v = t[x][y0 + i];
        __nv_bfloat16 h = __float2bfloat16(v);
        __nv_bfloat16 l = __float2bfloat16(v - __bfloat162float(h));
        size_t o = (size_t)(bx + y0 + i) * 2048 + by + x;
        Th[o] = h;
        Tl[o] = l;
    }
}

// ---------------------------------------------------------------------------
// RoPE + precision-split producer
// ---------------------------------------------------------------------------
__global__ __launch_bounds__(256) void rope_split_kernel(
    const float* __restrict__ qkv,
    float* __restrict__ kc, float* __restrict__ vc,
    __nv_bfloat16* __restrict__ Qhi, __nv_bfloat16* __restrict__ Qlo,
    __nv_bfloat16* __restrict__ Khi, __nv_bfloat16* __restrict__ Klo,
    __nv_bfloat16* __restrict__ Vhi, __nv_bfloat16* __restrict__ Vlo,
    const int* __restrict__ sp_ptr)
{
    const float LOG2_BASE_OVER_HALF = 13.287712379549449f / 64.0f;
    const float scale = 0.08838834764831845f;  // 1/sqrt(128)
    int m = blockIdx.x;
    int s = m & (S_ - 1);
    int sp = *sp_ptr;
    float pos = (float)(sp + s);
    int tid = threadIdx.x;

    for (int p = tid; p < H_ * 64; p += 256) {
        int h = p >> 6, e = p & 63;
        float inv = exp2f(-(float)e * LOG2_BASE_OVER_HALF);
        float ang = pos * inv;
        float sn, cs;
        sincosf(ang, &sn, &cs);
        const float* base = qkv + (size_t)m * NQKV + h * DH_;
        float x1 = base[e], x2 = base[e + 64];
        float y1 = (x1 * cs - x2 * sn) * scale;
        float y2 = (x1 * sn + x2 * cs) * scale;
        size_t o = (size_t)m * D_ + h * DH_;
        __nv_bfloat16 h1 = __float2bfloat16(y1);
        __nv_bfloat16 h2 = __float2bfloat16(y2);
        Qhi[o + e]      = h1;
        Qhi[o + e + 64] = h2;
        Qlo[o + e]      = __float2bfloat16(y1 - __bfloat162float(h1));
        Qlo[o + e + 64] = __float2bfloat16(y2 - __bfloat162float(h2));
    }
    for (int p = tid; p < KVH_ * 64; p += 256) {
        int h = p >> 6, e = p & 63;
        float inv = exp2f(-(float)e * LOG2_BASE_OVER_HALF);
        float ang = pos * inv;
        float sn, cs;
        sincosf(ang, &sn, &cs);
        const float* base = qkv + (size_t)m * NQKV + 2048 + h * DH_;
        float x1 = base[e], x2 = base[e + 64];
        float y1 = x1 * cs - x2 * sn;
        float y2 = x1 * sn + x2 * cs;
        size_t o = (size_t)m * (KVH_ * DH_) + h * DH_;
        kc[o + e]      = y1;
        kc[o + e + 64] = y2;
        __nv_bfloat16 h1 = __float2bfloat16(y1);
        __nv_bfloat16 h2 = __float2bfloat16(y2);
        Khi[o + e]      = h1;
        Khi[o + e + 64] = h2;
        Klo[o + e]      = __float2bfloat16(y1 - __bfloat162float(h1));
        Klo[o + e + 64] = __float2bfloat16(y2 - __bfloat162float(h2));
    }
    for (int i = tid; i < KVH_ * DH_; i += 256) {
        float v = qkv[(size_t)m * NQKV + 2560 + i];
        size_t o = (size_t)m * (KVH_ * DH_) + i;
        vc[o] = v;
        __nv_bfloat16 h = __float2bfloat16(v);
        Vhi[o] = h;
        Vlo[o] = __float2bfloat16(v - __bfloat162float(h));
    }
}

// ---------------------------------------------------------------------------
// Tensor-core flash attention, split-bf16 numerics.
// BM=64 (4 warps x m16), BN=32, Dh=128. Q fragments in registers.
// Double-buffered KV: stage = Khi|Klo|Vhi|Vlo each 32x128 bf16 (8KB) = 32KB.
// smem: Q hi/lo 32KB + 2 stages x 32KB = 96KB -> 2 CTAs/SM.
// ---------------------------------------------------------------------------
#define ATT_KV_STAGE 32768
#define ATT2_SMEM (32768 + 2 * ATT_KV_STAGE)

__global__ __launch_bounds__(128, 2) void attn_mma_kernel(
    const __nv_bfloat16* __restrict__ Qhi, const __nv_bfloat16* __restrict__ Qlo,
    const __nv_bfloat16* __restrict__ Khi, const __nv_bfloat16* __restrict__ Klo,
    const __nv_bfloat16* __restrict__ Vhi, const __nv_bfloat16* __restrict__ Vlo,
    __nv_bfloat16* __restrict__ Ohi, __nv_bfloat16* __restrict__ Olo,
    const int* __restrict__ sp_ptr)
{
    extern __shared__ char smem[];
    uint32_t sb = smem_u32(smem);
    const uint32_t sQh = sb, sQl = sb + 16384;
    const uint32_t sKV = sb + 32768;

    int tid = threadIdx.x;
    int lane = tid & 31;
    int warp = tid >> 5;                 // 0..3
    int bh = blockIdx.y;
    int b = bh >> 4, h = bh & 15, kvh = h >> 2;
    int q0 = blockIdx.x * 64;
    int sp = *sp_ptr;
    float slope = exp2f(-0.5f * (float)(h + 1));

    int fr = ((lane >> 3) & 1) * 8 + (lane & 7);
    int fs = lane >> 4;

    int kt_end = (sp + q0 + 63) >> 5;            // BN=32 tiles
    if (kt_end > S_ / 32 - 1) kt_end = S_ / 32 - 1;

    // ---- KV tile loader (32 rows x 128 cols, 4 mats) ----
    auto load_kv = [&](int kt) {
        int k0 = kt * 32;
        uint32_t stage = sKV + (uint32_t)(kt & 1) * ATT_KV_STAGE;
#pragma unroll
        for (int i = 0; i < 16; i++) {
            int idx = tid + i * 128;   // 0..2047
            int t = idx >> 9;          // 0 Khi 1 Klo 2 Vhi 3 Vlo
            int inner = idx & 511;
            int r = inner >> 4, sg = inner & 15;
            const __nv_bfloat16* basep =
                (t == 0) ? Khi : (t == 1) ? Klo : (t == 2) ? Vhi : Vlo;
            const __nv_bfloat16* src =
                basep + (size_t)(b * S_ + k0 + r) * 512 + kvh * 128 + sg * 8;
            cp16(stage + (uint32_t)t * 8192u + aswz(r, sg), src);
        }
        asm volatile("cp.async.commit_group;" ::: "memory");
    };

    // ---- prologue: Q (group 0), KV(0) (group 1), KV(1) (group 2) ----
#pragma unroll
    for (int i = 0; i < 16; i++) {
        int idx = tid + i * 128;          // 0..2047
        int t = idx >> 10;                // 0 hi, 1 lo
        int inner = idx & 1023;
        int r = inner >> 4, sg = inner & 15;
        const __nv_bfloat16* src = (t ? Qlo : Qhi)
            + (size_t)(b * S_ + q0 + r) * 2048 + h * 128 + sg * 8;
        cp16((t ? sQl : sQh) + aswz(r, sg), src);
    }
    asm volatile("cp.async.commit_group;" ::: "memory");
    load_kv(0);
    load_kv(1);     // kt_end >= 1 always

    // ---- Q fragments -> registers (kt-invariant) ----
    asm volatile("cp.async.wait_group 2;" ::: "memory");
    __syncthreads();
    uint32_t qh[8][4], ql[8][4];
#pragma unroll
    for (int s = 0; s < 8; s++) {
        ldm_x4(qh[s], sQh + aswz(warp * 16 + fr, 2 * s + fs));
        ldm_x4(ql[s], sQl + aswz(warp * 16 + fr, 2 * s + fs));
    }

    float Oacc[16][4];
#pragma unroll
    for (int e = 0; e < 16; e++)
#pragma unroll
        for (int k = 0; k < 4; k++) Oacc[e][k] = 0.f;
    float m0r = -1e30f, m1r = -1e30f;
    float l0r = 0.f, l1r = 0.f;

    int row0 = q0 + warp * 16 + (lane >> 2);
    int qp0 = sp + row0, qp1 = qp0 + 8;

    for (int kt = 0; kt <= kt_end; kt++) {
        int k0 = kt * 32;
        asm volatile("cp.async.wait_group 1;" ::: "memory");
        __syncthreads();

        uint32_t stage = sKV + (uint32_t)(kt & 1) * ATT_KV_STAGE;
        uint32_t sKh = stage, sKl = stage + 8192;
        uint32_t sVh = stage + 16384, sVl = stage + 24576;

        // ---- S = Q K^T (split: hh + hl + lh), 4 n8 frags ----
        float sacc[4][4];
#pragma unroll
        for (int nj = 0; nj < 4; nj++)
#pragma unroll
            for (int k = 0; k < 4; k++) sacc[nj][k] = 0.f;

#pragma unroll
        for (int s = 0; s < 8; s++) {
            uint32_t kbh[4][2], kbl[4][2], t4[4];
#pragma unroll
            for (int j = 0; j < 2; j++) {
                ldm_x4(t4, sKh + aswz(j * 16 + fr, 2 * s + fs));
                kbh[2 * j][0] = t4[0]; kbh[2 * j][1] = t4[2];
                kbh[2 * j + 1][0] = t4[1]; kbh[2 * j + 1][1] = t4[3];
                ldm_x4(t4, sKl + aswz(j * 16 + fr, 2 * s + fs));
                kbl[2 * j][0] = t4[0]; kbl[2 * j][1] = t4[2];
                kbl[2 * j + 1][0] = t4[1]; kbl[2 * j + 1][1] = t4[3];
            }
#pragma unroll
            for (int nj = 0; nj < 4; nj++) {
                mma_bf16(sacc[nj], qh[s], kbh[nj][0], kbh[nj][1]);
                mma_bf16(sacc[nj], qh[s], kbl[nj][0], kbl[nj][1]);
                mma_bf16(sacc[nj], ql[s], kbh[nj][0], kbh[nj][1]);
            }
        }

        // ---- bias + causal mask ----
#pragma unroll
        for (int nj = 0; nj < 4; nj++) {
            int c = k0 + nj * 8 + (lane & 3) * 2;
            sacc[nj][0] = (c     <= qp0) ? sacc[nj][0] - slope * (float)(qp0 - c)     : -1e30f;
            sacc[nj][1] = (c + 1 <= qp0) ? sacc[nj][1] - slope * (float)(qp0 - c - 1) : -1e30f;
            sacc[nj][2] = (c     <= qp1) ? sacc[nj][2] - slope * (float)(qp1 - c)     : -1e30f;
            sacc[nj][3] = (c + 1 <= qp1) ? sacc[nj][3] - slope * (float)(qp1 - c - 1) : -1e30f;
        }

        // ---- online softmax ----
        float mx0 = -1e30f, mx1 = -1e30f;
#pragma unroll
        for (int nj = 0; nj < 4; nj++) {
            mx0 = fmaxf(mx0, fmaxf(sacc[nj][0], sacc[nj][1]));
            mx1 = fmaxf(mx1, fmaxf(sacc[nj][2], sacc[nj][3]));
        }
        mx0 = fmaxf(mx0, __shfl_xor_sync(0xffffffffu, mx0, 1));
        mx0 = fmaxf(mx0, __shfl_xor_sync(0xffffffffu, mx0, 2));
        mx1 = fmaxf(mx1, __shfl_xor_sync(0xffffffffu, mx1, 1));
        mx1 = fmaxf(mx1, __shfl_xor_sync(0xffffffffu, mx1, 2));
        float mn0 = fmaxf(m0r, mx0), mn1 = fmaxf(m1r, mx1);
        float corr0 = __expf(m0r - mn0), corr1 = __expf(m1r - mn1);
        m0r = mn0; m1r = mn1;

        float ls0 = 0.f, ls1 = 0.f;
#pragma unroll
        for (int nj = 0; nj < 4; nj++) {
            sacc[nj][0] = __expf(sacc[nj][0] - mn0);
            sacc[nj][1] = __expf(sacc[nj][1] - mn0);
            sacc[nj][2] = __expf(sacc[nj][2] - mn1);
            sacc[nj][3] = __expf(sacc[nj][3] - mn1);
            ls0 += sacc[nj][0] + sacc[nj][1];
            ls1 += sacc[nj][2] + sacc[nj][3];
        }
        ls0 += __shfl_xor_sync(0xffffffffu, ls0, 1);
        ls0 += __shfl_xor_sync(0xffffffffu, ls0, 2);
        ls1 += __shfl_xor_sync(0xffffffffu, ls1, 1);
        ls1 += __shfl_xor_sync(0xffffffffu, ls1, 2);
        l0r = l0r * corr0 + ls0;
        l1r = l1r * corr1 + ls1;

#pragma unroll
        for (int e = 0; e < 16; e++) {
            Oacc[e][0] *= corr0; Oacc[e][1] *= corr0;
            Oacc[e][2] *= corr1; Oacc[e][3] *= corr1;
        }

        // ---- P -> bf16 hi/lo A-fragments (2 k16 tiles) ----
        uint32_t phi[2][4], plo[2][4];
#pragma unroll
        for (int t = 0; t < 2; t++) {
            float r0, r1;
            phi[t][0] = pack_hi2(sacc[2 * t][0], sacc[2 * t][1], r0, r1);
            plo[t][0] = pack_bf2(r0, r1);
            phi[t][1] = pack_hi2(sacc[2 * t][2], sacc[2 * t][3], r0, r1);
            plo[t][1] = pack_bf2(r0, r1);
            phi[t][2] = pack_hi2(sacc[2 * t + 1][0], sacc[2 * t + 1][1], r0, r1);
            plo[t][2] = pack_bf2(r0, r1);
            phi[t][3] = pack_hi2(sacc[2 * t + 1][2], sacc[2 * t + 1][3], r0, r1);
            plo[t][3] = pack_bf2(r0, r1);
        }

        // ---- O += P V (split: hh + hl + lh) ----
#pragma unroll
        for (int t = 0; t < 2; t++) {
#pragma unroll
            for (int u = 0; u < 8; u++) {
                uint32_t th[4], tl[4];
                ldm_x4_t(th, sVh + aswz(t * 16 + fr, 2 * u + fs));
                ldm_x4_t(tl, sVl + aswz(t * 16 + fr, 2 * u + fs));
                mma_bf16(Oacc[2 * u], phi[t], th[0], th[1]);
                mma_bf16(Oacc[2 * u], phi[t], tl[0], tl[1]);
                mma_bf16(Oacc[2 * u], plo[t], th[0], th[1]);
                mma_bf16(Oacc[2 * u + 1], phi[t], th[2], th[3]);
                mma_bf16(Oacc[2 * u + 1], phi[t], tl[2], tl[3]);
                mma_bf16(Oacc[2 * u + 1], plo[t], th[2], th[3]);
            }
        }
        __syncthreads();
        if (kt + 2 <= kt_end) load_kv(kt + 2);
        else asm volatile("cp.async.commit_group;" ::: "memory");
    }

    // ---- epilogue: normalize + split to bf16 hi/lo ----
    float inv0 = 1.f / l0r, inv1 = 1.f / l1r;
    size_t row0g = (size_t)(b * S_ + row0);
#pragma unroll
    for (int e = 0; e < 16; e++) {
        int colb = h * 128 + e * 8 + (lane & 3) * 2;
        float x0 = Oacc[e][0] * inv0, x1 = Oacc[e][1] * inv0;
        float x2 = Oacc[e][2] * inv1, x3 = Oacc[e][3] * inv1;
        float r0, r1;
        uint32_t hp0 = pack_hi2(x0, x1, r0, r1);
        uint32_t lp0 = pack_bf2(r0, r1);
        uint32_t hp1 = pack_hi2(x2, x3, r0, r1);
        uint32_t lp1 = pack_bf2(r0, r1);
        *(uint32_t*)&Ohi[row0g * 2048 + colb] = hp0;
        *(uint32_t*)&Olo[row0g * 2048 + colb] = lp0;
        *(uint32_t*)&Ohi[(row0g + 8) * 2048 + colb] = hp1;
        *(uint32_t*)&Olo[(row0g + 8) * 2048 + colb] = lp1;
    }
}

// ---------------------------------------------------------------------------
extern "C" void kernel_launch(void* const* d_in, const int* in_sizes, int n_in,
                              void* d_out, int out_size)
{
    const float* residual = (const float*)d_in[0];
    const float* W_Q = (const float*)d_in[1];
    const float* W_K = (const float*)d_in[2];
    const float* W_V = (const float*)d_in[3];
    const float* W_O = (const float*)d_in[4];
    const int* sp = (const int*)d_in[5];

    float* out = (float*)d_out;
    float* k_cache = out + (size_t)B_ * S_ * D_;
    float* v_cache = k_cache + (size_t)B_ * S_ * KVH_ * DH_;

    float* qkv_ptr;
    __nv_bfloat16 *Ahi, *Alo, *Whi, *Wlo, *WOhi, *WOlo, *Phi, *Plo;
    __nv_bfloat16 *Khi, *Klo, *Vhi, *Vlo;
    cudaGetSymbolAddress((void**)&qkv_ptr, g_qkv);
    cudaGetSymbolAddress((void**)&Ahi, g_Ahi);
    cudaGetSymbolAddress((void**)&Alo, g_Alo);
    cudaGetSymbolAddress((void**)&Whi, g_Whi);
    cudaGetSymbolAddress((void**)&Wlo, g_Wlo);
    cudaGetSymbolAddress((void**)&WOhi, g_WOhi);
    cudaGetSymbolAddress((void**)&WOlo, g_WOlo);
    cudaGetSymbolAddress((void**)&Phi, g_Phi);
    cudaGetSymbolAddress((void**)&Plo, g_Plo);
    cudaGetSymbolAddress((void**)&Khi, g_Khi);
    cudaGetSymbolAddress((void**)&Klo, g_Klo);
    cudaGetSymbolAddress((void**)&Vhi, g_Vhi);
    cudaGetSymbolAddress((void**)&Vlo, g_Vlo);

    cudaFuncSetAttribute(hmma_gemm, cudaFuncAttributeMaxDynamicSharedMemorySize,
                         GEMM_SMEM);
    cudaFuncSetAttribute(attn_mma_kernel, cudaFuncAttributeMaxDynamicSharedMemorySize,
                         ATT2_SMEM);

    // 0) splits
    split_kernel<<<(M_ * D_ / 4 + 255) / 256, 256>>>(residual, Ahi, Alo, M_ * D_ / 4);
    split_kernel<<<(2048 * 2048 / 4 + 255) / 256, 256>>>(W_Q, Whi, Wlo, 2048 * 2048 / 4);
    split_kernel<<<(512 * 2048 / 4 + 255) / 256, 256>>>(
        W_K, Whi + (size_t)2048 * 2048, Wlo + (size_t)2048 * 2048, 512 * 2048 / 4);
    split_kernel<<<(512 * 2048 / 4 + 255) / 256, 256>>>(
        W_V, Whi + (size_t)2560 * 2048, Wlo + (size_t)2560 * 2048, 512 * 2048 / 4);
    transpose_split_wo<<<dim3(64, 64), 256>>>(W_O, WOhi, WOlo);

    // 1) fused QKV projection
    hmma_gemm<<<dim3(NQKV / 128, M_ / 128), 256, GEMM_SMEM>>>(
        Ahi, Alo, Whi, Wlo, qkv_ptr, NQKV);

    // 2) RoPE + split producer (reuses Ahi/Alo as Qhi/Qlo)
    rope_split_kernel<<<M_, 256>>>(qkv_ptr, k_cache, v_cache,
                                   Ahi, Alo, Khi, Klo, Vhi, Vlo, sp);

    // 3) tensor-core attention -> bf16 hi/lo output (Phi/Plo)
    attn_mma_kernel<<<dim3(S_ / 64, B_ * H_), 128, ATT2_SMEM>>>(
        Ahi, Alo, Khi, Klo, Vhi, Vlo, Phi, Plo, sp);

    // 4) output projection
    hmma_gemm<<<dim3(D_ / 128, M_ / 128), 256, GEMM_SMEM>>>(
        Phi, Plo, WOhi, WOlo, out, D_);
}

// round 7
// speedup vs baseline: 1.4943x; 1.4426x over previous
#include <cuda_runtime.h>
#include <cuda_fp16.h>
#include <math.h>
#include <stdint.h>

// Problem constants (fixed shapes from setup_inputs)
#define B_   2
#define S_   2048
#define D_   2048
#define H_   16
#define KVH_ 4
#define DH_  128
#define M_   (B_ * S_)          // 4096
#define NQKV 3072               // 2048 q + 512 k + 512 v

// Scratch (static device arrays; no runtime allocation allowed)
__device__ float g_qkv[M_ * NQKV];
__device__ __half g_Ahi[M_ * D_];     // residual hi; reused as Q hi after rope
__device__ __half g_Alo[M_ * D_];     // residual lo; reused as Q lo after rope
__device__ __half g_Whi[NQKV * D_];   // W_Q|W_K|W_V rows, fp16 (no lo needed)
__device__ __half g_WOhi[D_ * D_];    // W_O transposed [d][he], fp16
__device__ __half g_Phi[M_ * D_];     // attention output hi
__device__ __half g_Plo[M_ * D_];     // attention output lo
__device__ __half g_Khi[M_ * 512];
__device__ __half g_Vhi[M_ * 512];

// ---------------------------------------------------------------------------
// helpers
// ---------------------------------------------------------------------------
__device__ __forceinline__ uint32_t smem_u32(const void* p) {
    uint32_t a;
    asm("{ .reg .u64 t; cvta.to.shared.u64 t, %1; cvt.u32.u64 %0, t; }"
        : "=r"(a) : "l"(p));
    return a;
}

__device__ __forceinline__ void cp16(uint32_t dst, const void* src) {
    asm volatile("cp.async.cg.shared.global [%0], [%1], 16;"
                 :: "r"(dst), "l"(src));
}

__device__ __forceinline__ void ldm_x4(uint32_t* r, uint32_t addr) {
    asm volatile("ldmatrix.sync.aligned.m8n8.x4.shared.b16 {%0,%1,%2,%3}, [%4];"
                 : "=r"(r[0]), "=r"(r[1]), "=r"(r[2]), "=r"(r[3]) : "r"(addr));
}

__device__ __forceinline__ void ldm_x4_t(uint32_t* r, uint32_t addr) {
    asm volatile("ldmatrix.sync.aligned.m8n8.x4.trans.shared.b16 {%0,%1,%2,%3}, [%4];"
                 : "=r"(r[0]), "=r"(r[1]), "=r"(r[2]), "=r"(r[3]) : "r"(addr));
}

__device__ __forceinline__ void mma_f16(float* c, const uint32_t* a,
                                        uint32_t b0, uint32_t b1) {
    asm volatile(
        "mma.sync.aligned.m16n8k16.row.col.f32.f16.f16.f32 "
        "{%0,%1,%2,%3}, {%4,%5,%6,%7}, {%8,%9}, {%0,%1,%2,%3};"
        : "+f"(c[0]), "+f"(c[1]), "+f"(c[2]), "+f"(c[3])
        : "r"(a[0]), "r"(a[1]), "r"(a[2]), "r"(a[3]), "r"(b0), "r"(b1));
}

// swizzled byte offset for a 16B segment (row r, seg s) in a [rows][32]fp16 block
__device__ __forceinline__ uint32_t swz_off(int r, int s) {
    return (uint32_t)(r * 64 + ((s ^ ((r >> 1) & 3)) * 16));
}

// swizzled byte offset for [rows][128 fp16] tiles (256B rows, 16 segs)
__device__ __forceinline__ uint32_t aswz(int r, int sg) {
    return (uint32_t)(r * 256 + ((sg ^ (r & 7)) * 16));
}

__device__ __forceinline__ uint32_t pack_hi2(float x0, float x1, float& r0, float& r1) {
    __half h0 = __float2half_rn(x0);
    __half h1 = __float2half_rn(x1);
    r0 = x0 - __half2float(h0);
    r1 = x1 - __half2float(h1);
    __half2 p = __halves2half2(h0, h1);
    return *(uint32_t*)&p;
}

__device__ __forceinline__ uint32_t pack_f2h2(float x0, float x1) {
    __half2 p = __floats2half2_rn(x0, x1);
    return *(uint32_t*)&p;
}

// ---------------------------------------------------------------------------
// HMMA GEMM: C[m,n] = sum_k A[m,k]*B[n,k], fp32 via fp16 2-pass (ah*bh + al*bh)
// CTA tile 128x128, 8 warps (4m x 2n), warp tile 32x64. K-chunk 32.
// stage = Ah|Al|Bh, each [128][32]fp16 (8KB) = 24KB; 3 stages = 72KB. 2 CTA/SM.
// ---------------------------------------------------------------------------
#define GEMM_STAGE 24576
#define GEMM_SMEM (3 * GEMM_STAGE)

__global__ __launch_bounds__(256, 2) void hmma_gemm(
    const __half* __restrict__ Ah, const __half* __restrict__ Al,
    const __half* __restrict__ Bh,
    float* __restrict__ C, int ldc)
{
    extern __shared__ char smem[];
    uint32_t sb = smem_u32(smem);

    int tid = threadIdx.x;
    int lane = tid & 31;
    int warp = tid >> 5;
    int warp_m = warp & 3;
    int warp_n = warp >> 2;
    int m0 = blockIdx.y * 128;
    int n0 = blockIdx.x * 128;

    int q = lane >> 3;
    int lrow = lane & 7;
    int arow_l = (q & 1) * 8 + lrow;
    int ksel = q >> 1;

    float acc[2][8][4];
#pragma unroll
    for (int i = 0; i < 2; i++)
#pragma unroll
        for (int j = 0; j < 8; j++)
#pragma unroll
            for (int k = 0; k < 4; k++) acc[i][j][k] = 0.f;

    auto load_chunk = [&](int c) {
        int k0 = c * 32;
        uint32_t buf = sb + (uint32_t)(c % 3) * GEMM_STAGE;
#pragma unroll
        for (int t = 0; t < 6; t++) {
            int g = tid + t * 256;           // 0..1535
            int mat = g >> 9;                // 0 Ah, 1 Al, 2 Bh
            int inner = g & 511;
            int r = inner >> 2;
            int s = inner & 3;
            const __half* base = (mat == 0) ? Ah : (mat == 1) ? Al : Bh;
            int row = ((mat < 2) ? m0 : n0) + r;
            const void* src = base + (size_t)row * 2048 + k0 + s * 8;
            cp16(buf + (uint32_t)mat * 8192u + swz_off(r, s), src);
        }
        asm volatile("cp.async.commit_group;" ::: "memory");
    };

    load_chunk(0);
    load_chunk(1);
    load_chunk(2);

    for (int c = 0; c < 64; c++) {
        asm volatile("cp.async.wait_group 2;" ::: "memory");
        __syncthreads();

        uint32_t buf = sb + (uint32_t)(c % 3) * GEMM_STAGE;
        uint32_t bAh = buf, bAl = buf + 8192, bBh = buf + 16384;

#pragma unroll
        for (int ks = 0; ks < 2; ks++) {
            int s = ks * 2 + ksel;
            uint32_t ah[2][4], al[2][4];
#pragma unroll
            for (int mi = 0; mi < 2; mi++) {
                int r = warp_m * 32 + mi * 16 + arow_l;
                ldm_x4(ah[mi], bAh + swz_off(r, s));
                ldm_x4(al[mi], bAl + swz_off(r, s));
            }
            uint32_t bh[8][2];
#pragma unroll
            for (int j = 0; j < 4; j++) {
                int r = warp_n * 64 + j * 16 + arow_l;
                uint32_t t4[4];
                ldm_x4(t4, bBh + swz_off(r, s));
                bh[j * 2 + 0][0] = t4[0]; bh[j * 2 + 0][1] = t4[2];
                bh[j * 2 + 1][0] = t4[1]; bh[j * 2 + 1][1] = t4[3];
            }
#pragma unroll
            for (int mi = 0; mi < 2; mi++) {
#pragma unroll
                for (int nj = 0; nj < 8; nj++) {
                    mma_f16(acc[mi][nj], ah[mi], bh[nj][0], bh[nj][1]);
                    mma_f16(acc[mi][nj], al[mi], bh[nj][0], bh[nj][1]);
                }
            }
        }
        __syncthreads();
        if (c + 3 < 64) load_chunk(c + 3);
        else asm volatile("cp.async.commit_group;" ::: "memory");
    }

    int rr = lane >> 2;
    int cc = (lane & 3) * 2;
#pragma unroll
    for (int mi = 0; mi < 2; mi++) {
        int r1 = m0 + warp_m * 32 + mi * 16 + rr;
#pragma unroll
        for (int nj = 0; nj < 8; nj++) {
            int col = n0 + warp_n * 64 + nj * 8 + cc;
            float2 v0 = make_float2(acc[mi][nj][0], acc[mi][nj][1]);
            float2 v1 = make_float2(acc[mi][nj][2], acc[mi][nj][3]);
            *(float2*)&C[(size_t)r1 * ldc + col] = v0;
            *(float2*)&C[(size_t)(r1 + 8) * ldc + col] = v1;
        }
    }
}

// ---------------------------------------------------------------------------
// Elementwise fp32 -> (fp16 hi, fp16 lo) split
// ---------------------------------------------------------------------------
__global__ __launch_bounds__(256) void split_kernel(
    const float* __restrict__ src, __half* __restrict__ hi,
    __half* __restrict__ lo, int n4)
{
    int i = blockIdx.x * 256 + threadIdx.x;
    if (i >= n4) return;
    float4 v = ((const float4*)src)[i];
    __half h0 = __float2half_rn(v.x);
    __half h1 = __float2half_rn(v.y);
    __half h2 = __float2half_rn(v.z);
    __half h3 = __float2half_rn(v.w);
    __half l0 = __float2half_rn(v.x - __half2float(h0));
    __half l1 = __float2half_rn(v.y - __half2float(h1));
    __half l2 = __float2half_rn(v.z - __half2float(h2));
    __half l3 = __float2half_rn(v.w - __half2float(h3));
    ushort4 hv = make_ushort4(__half_as_ushort(h0), __half_as_ushort(h1),
                              __half_as_ushort(h2), __half_as_ushort(h3));
    ushort4 lv = make_ushort4(__half_as_ushort(l0), __half_as_ushort(l1),
                              __half_as_ushort(l2), __half_as_ushort(l3));
    ((ushort4*)hi)[i] = hv;
    ((ushort4*)lo)[i] = lv;
}

// ---------------------------------------------------------------------------
// Elementwise fp32 -> fp16 (hi only) for weights
// ---------------------------------------------------------------------------
__global__ __launch_bounds__(256) void cvt_kernel(
    const float* __restrict__ src, __half* __restrict__ dst, int n4)
{
    int i = blockIdx.x * 256 + threadIdx.x;
    if (i >= n4) return;
    float4 v = ((const float4*)src)[i];
    ushort4 hv = make_ushort4(
        __half_as_ushort(__float2half_rn(v.x)),
        __half_as_ushort(__float2half_rn(v.y)),
        __half_as_ushort(__float2half_rn(v.z)),
        __half_as_ushort(__float2half_rn(v.w)));
    ((ushort4*)dst)[i] = hv;
}

// ---------------------------------------------------------------------------
// Transpose + convert W_O: in [he=2048][d=2048] fp32 -> out [d][he] fp16
// ---------------------------------------------------------------------------
__global__ __launch_bounds__(256) void transpose_cvt_wo(
    const float* __restrict__ W, __half* __restrict__ Th)
{
    __shared__ float t[32][33];
    int bx = blockIdx.x * 32;
    int by = blockIdx.y * 32;
    int x = threadIdx.x & 31;
    int y0 = threadIdx.x >> 5;
#pragma unroll
    for (int i = 0; i < 32; i += 8)
        t[y0 + i][x] = W[(size_t)(by + y0 + i) * 2048 + bx + x];
    __syncthreads();
#pragma unroll
    for (int i = 0; i < 32; i += 8) {
        float v = t[x][y0 + i];
        Th[(size_t)(bx + y0 + i) * 2048 + by + x] = __float2half_rn(v);
    }
}

// ---------------------------------------------------------------------------
// RoPE + precision-split producer:
//  q: rope, scale 1/sqrt(Dh), split -> Qhi/Qlo (reuses g_Ahi/g_Alo)
//  k: rope -> fp32 k_cache + fp16 Khi
//  v: copy -> fp32 v_cache + fp16 Vhi
// ---------------------------------------------------------------------------
__global__ __launch_bounds__(256) void rope_split_kernel(
    const float* __restrict__ qkv,
    float* __restrict__ kc, float* __restrict__ vc,
    __half* __restrict__ Qhi, __half* __restrict__ Qlo,
    __half* __restrict__ Khi, __half* __restrict__ Vhi,
    const int* __restrict__ sp_ptr)
{
    const float LOG2_BASE_OVER_HALF = 13.287712379549449f / 64.0f;
    const float scale = 0.08838834764831845f;  // 1/sqrt(128)
    int m = blockIdx.x;
    int s = m & (S_ - 1);
    int sp = *sp_ptr;
    float pos = (float)(sp + s);
    int tid = threadIdx.x;

    for (int p = tid; p < H_ * 64; p += 256) {
        int h = p >> 6, e = p & 63;
        float inv = exp2f(-(float)e * LOG2_BASE_OVER_HALF);
        float ang = pos * inv;
        float sn, cs;
        sincosf(ang, &sn, &cs);
        const float* base = qkv + (size_t)m * NQKV + h * DH_;
        float x1 = base[e], x2 = base[e + 64];
        float y1 = (x1 * cs - x2 * sn) * scale;
        float y2 = (x1 * sn + x2 * cs) * scale;
        size_t o = (size_t)m * D_ + h * DH_;
        __half h1 = __float2half_rn(y1);
        __half h2 = __float2half_rn(y2);
        Qhi[o + e]      = h1;
        Qhi[o + e + 64] = h2;
        Qlo[o + e]      = __float2half_rn(y1 - __half2float(h1));
        Qlo[o + e + 64] = __float2half_rn(y2 - __half2float(h2));
    }
    for (int p = tid; p < KVH_ * 64; p += 256) {
        int h = p >> 6, e = p & 63;
        float inv = exp2f(-(float)e * LOG2_BASE_OVER_HALF);
        float ang = pos * inv;
        float sn, cs;
        sincosf(ang, &sn, &cs);
        const float* base = qkv + (size_t)m * NQKV + 2048 + h * DH_;
        float x1 = base[e], x2 = base[e + 64];
        float y1 = x1 * cs - x2 * sn;
        float y2 = x1 * sn + x2 * cs;
        size_t o = (size_t)m * (KVH_ * DH_) + h * DH_;
        kc[o + e]      = y1;
        kc[o + e + 64] = y2;
        Khi[o + e]      = __float2half_rn(y1);
        Khi[o + e + 64] = __float2half_rn(y2);
    }
    for (int i = tid; i < KVH_ * DH_; i += 256) {
        float v = qkv[(size_t)m * NQKV + 2560 + i];
        size_t o = (size_t)m * (KVH_ * DH_) + i;
        vc[o] = v;
        Vhi[o] = __float2half_rn(v);
    }
}

// ---------------------------------------------------------------------------
// Tensor-core flash attention, fp16 2-pass numerics.
// BM=64 (4 warps x m16), BN=64, Dh=128. Q frags hoisted to registers.
// KV stage = Khi|Vhi each 64x128 fp16 (16KB) = 32KB; 2 stages.
// smem: Q hi/lo 32KB + 64KB = 96KB -> 2 CTAs/SM.
// ---------------------------------------------------------------------------
#define ATT_KV_STAGE 32768
#define ATT2_SMEM (32768 + 2 * ATT_KV_STAGE)

__global__ __launch_bounds__(128, 2) void attn_mma_kernel(
    const __half* __restrict__ Qhi, const __half* __restrict__ Qlo,
    const __half* __restrict__ Khi, const __half* __restrict__ Vhi,
    __half* __restrict__ Ohi, __half* __restrict__ Olo,
    const int* __restrict__ sp_ptr)
{
    extern __shared__ char smem[];
    uint32_t sb = smem_u32(smem);
    const uint32_t sQh = sb, sQl = sb + 16384;
    const uint32_t sKV = sb + 32768;

    int tid = threadIdx.x;
    int lane = tid & 31;
    int warp = tid >> 5;                 // 0..3
    int bh = blockIdx.y;
    int b = bh >> 4, h = bh & 15, kvh = h >> 2;
    int q0 = blockIdx.x * 64;
    int sp = *sp_ptr;
    float slope = exp2f(-0.5f * (float)(h + 1));

    int fr = ((lane >> 3) & 1) * 8 + (lane & 7);
    int fs = lane >> 4;

    int kt_end = (sp + q0 + 63) >> 6;
    if (kt_end > S_ / 64 - 1) kt_end = S_ / 64 - 1;

    // ---- KV tile loader (Khi + Vhi, 64 rows x 128 cols each) ----
    auto load_kv = [&](int kt) {
        int k0 = (kt <= kt_end ? kt : kt_end) * 64;
        uint32_t stage = sKV + (uint32_t)(kt & 1) * ATT_KV_STAGE;
#pragma unroll
        for (int i = 0; i < 16; i++) {
            int idx = tid + i * 128;   // 0..2047
            int t = idx >> 10;         // 0 Khi, 1 Vhi
            int inner = idx & 1023;
            int r = inner >> 4, sg = inner & 15;
            const __half* basep = t ? Vhi : Khi;
            const __half* src =
                basep + (size_t)(b * S_ + k0 + r) * 512 + kvh * 128 + sg * 8;
            cp16(stage + (uint32_t)t * 16384u + aswz(r, sg), src);
        }
        asm volatile("cp.async.commit_group;" ::: "memory");
    };

    // ---- prologue: Q (group 0), KV(0) (group 1), KV(1) (group 2) ----
#pragma unroll
    for (int i = 0; i < 16; i++) {
        int idx = tid + i * 128;          // 0..2047
        int t = idx >> 10;                // 0 hi, 1 lo
        int inner = idx & 1023;
        int r = inner >> 4, sg = inner & 15;
        const __half* src = (t ? Qlo : Qhi)
            + (size_t)(b * S_ + q0 + r) * 2048 + h * 128 + sg * 8;
        cp16((t ? sQl : sQh) + aswz(r, sg), src);
    }
    asm volatile("cp.async.commit_group;" ::: "memory");
    load_kv(0);
    load_kv(1);

    // ---- Q fragments -> registers (kt-invariant) ----
    asm volatile("cp.async.wait_group 2;" ::: "memory");
    __syncthreads();
    uint32_t qh[8][4], ql[8][4];
#pragma unroll
    for (int s = 0; s < 8; s++) {
        ldm_x4(qh[s], sQh + aswz(warp * 16 + fr, 2 * s + fs));
        ldm_x4(ql[s], sQl + aswz(warp * 16 + fr, 2 * s + fs));
    }

    float Oacc[16][4];
#pragma unroll
    for (int e = 0; e < 16; e++)
#pragma unroll
        for (int k = 0; k < 4; k++) Oacc[e][k] = 0.f;
    float m0r = -1e30f, m1r = -1e30f;
    float l0r = 0.f, l1r = 0.f;

    int row0 = q0 + warp * 16 + (lane >> 2);
    int qp0 = sp + row0, qp1 = qp0 + 8;

    for (int kt = 0; kt <= kt_end; kt++) {
        int k0 = kt * 64;
        asm volatile("cp.async.wait_group 1;" ::: "memory");
        __syncthreads();

        uint32_t stage = sKV + (uint32_t)(kt & 1) * ATT_KV_STAGE;
        uint32_t sKh = stage, sVh = stage + 16384;

        // ---- S = Q K^T (2-pass: qh*kh + ql*kh) ----
        float sacc[8][4];
#pragma unroll
        for (int nj = 0; nj < 8; nj++)
#pragma unroll
            for (int k = 0; k < 4; k++) sacc[nj][k] = 0.f;

#pragma unroll
        for (int s = 0; s < 8; s++) {
            uint32_t kbh[8][2], t4[4];
#pragma unroll
            for (int j = 0; j < 4; j++) {
                ldm_x4(t4, sKh + aswz(j * 16 + fr, 2 * s + fs));
                kbh[2 * j][0] = t4[0]; kbh[2 * j][1] = t4[2];
                kbh[2 * j + 1][0] = t4[1]; kbh[2 * j + 1][1] = t4[3];
            }
#pragma unroll
            for (int nj = 0; nj < 8; nj++) {
                mma_f16(sacc[nj], qh[s], kbh[nj][0], kbh[nj][1]);
                mma_f16(sacc[nj], ql[s], kbh[nj][0], kbh[nj][1]);
            }
        }

        // ---- bias + causal mask ----
#pragma unroll
        for (int nj = 0; nj < 8; nj++) {
            int c = k0 + nj * 8 + (lane & 3) * 2;
            sacc[nj][0] = (c     <= qp0) ? sacc[nj][0] - slope * (float)(qp0 - c)     : -1e30f;
            sacc[nj][1] = (c + 1 <= qp0) ? sacc[nj][1] - slope * (float)(qp0 - c - 1) : -1e30f;
            sacc[nj][2] = (c     <= qp1) ? sacc[nj][2] - slope * (float)(qp1 - c)     : -1e30f;
            sacc[nj][3] = (c + 1 <= qp1) ? sacc[nj][3] - slope * (float)(qp1 - c - 1) : -1e30f;
        }

        // ---- online softmax ----
        float mx0 = -1e30f, mx1 = -1e30f;
#pragma unroll
        for (int nj = 0; nj < 8; nj++) {
            mx0 = fmaxf(mx0, fmaxf(sacc[nj][0], sacc[nj][1]));
            mx1 = fmaxf(mx1, fmaxf(sacc[nj][2], sacc[nj][3]));
        }
        mx0 = fmaxf(mx0, __shfl_xor_sync(0xffffffffu, mx0, 1));
        mx0 = fmaxf(mx0, __shfl_xor_sync(0xffffffffu, mx0, 2));
        mx1 = fmaxf(mx1, __shfl_xor_sync(0xffffffffu, mx1, 1));
        mx1 = fmaxf(mx1, __shfl_xor_sync(0xffffffffu, mx1, 2));
        float mn0 = fmaxf(m0r, mx0), mn1 = fmaxf(m1r, mx1);
        float corr0 = __expf(m0r - mn0), corr1 = __expf(m1r - mn1);
        m0r = mn0; m1r = mn1;

        float ls0 = 0.f, ls1 = 0.f;
#pragma unroll
        for (int nj = 0; nj < 8; nj++) {
            sacc[nj][0] = __expf(sacc[nj][0] - mn0);
            sacc[nj][1] = __expf(sacc[nj][1] - mn0);
            sacc[nj][2] = __expf(sacc[nj][2] - mn1);
            sacc[nj][3] = __expf(sacc[nj][3] - mn1);
            ls0 += sacc[nj][0] + sacc[nj][1];
            ls1 += sacc[nj][2] + sacc[nj][3];
        }
        ls0 += __shfl_xor_sync(0xffffffffu, ls0, 1);
        ls0 += __shfl_xor_sync(0xffffffffu, ls0, 2);
        ls1 += __shfl_xor_sync(0xffffffffu, ls1, 1);
        ls1 += __shfl_xor_sync(0xffffffffu, ls1, 2);
        l0r = l0r * corr0 + ls0;
        l1r = l1r * corr1 + ls1;

#pragma unroll
        for (int e = 0; e < 16; e++) {
            Oacc[e][0] *= corr0; Oacc[e][1] *= corr0;
            Oacc[e][2] *= corr1; Oacc[e][3] *= corr1;
        }

        // ---- P -> fp16 hi/lo A-fragments (4 k16 tiles) ----
        uint32_t phi[4][4], plo[4][4];
#pragma unroll
        for (int t = 0; t < 4; t++) {
            float r0, r1;
            phi[t][0] = pack_hi2(sacc[2 * t][0], sacc[2 * t][1], r0, r1);
            plo[t][0] = pack_f2h2(r0, r1);
            phi[t][1] = pack_hi2(sacc[2 * t][2], sacc[2 * t][3], r0, r1);
            plo[t][1] = pack_f2h2(r0, r1);
            phi[t][2] = pack_hi2(sacc[2 * t + 1][0], sacc[2 * t + 1][1], r0, r1);
            plo[t][2] = pack_f2h2(r0, r1);
            phi[t][3] = pack_hi2(sacc[2 * t + 1][2], sacc[2 * t + 1][3], r0, r1);
            plo[t][3] = pack_f2h2(r0, r1);
        }

        // ---- O += P V (2-pass: ph*vh + pl*vh) ----
#pragma unroll
        for (int t = 0; t < 4; t++) {
#pragma unroll
            for (int u = 0; u < 8; u++) {
                uint32_t th[4];
                ldm_x4_t(th, sVh + aswz(t * 16 + fr, 2 * u + fs));
                mma_f16(Oacc[2 * u], phi[t], th[0], th[1]);
                mma_f16(Oacc[2 * u], plo[t], th[0], th[1]);
                mma_f16(Oacc[2 * u + 1], phi[t], th[2], th[3]);
                mma_f16(Oacc[2 * u + 1], plo[t], th[2], th[3]);
            }
        }
        __syncthreads();
        if (kt + 2 <= kt_end) load_kv(kt + 2);
        else asm volatile("cp.async.commit_group;" ::: "memory");
    }

    // ---- epilogue: normalize + split to fp16 hi/lo ----
    float inv0 = 1.f / l0r, inv1 = 1.f / l1r;
    size_t row0g = (size_t)(b * S_ + row0);
#pragma unroll
    for (int e = 0; e < 16; e++) {
        int colb = h * 128 + e * 8 + (lane & 3) * 2;
        float x0 = Oacc[e][0] * inv0, x1 = Oacc[e][1] * inv0;
        float x2 = Oacc[e][2] * inv1, x3 = Oacc[e][3] * inv1;
        float r0, r1;
        uint32_t hp0 = pack_hi2(x0, x1, r0, r1);
        uint32_t lp0 = pack_f2h2(r0, r1);
        uint32_t hp1 = pack_hi2(x2, x3, r0, r1);
        uint32_t lp1 = pack_f2h2(r0, r1);
        *(uint32_t*)&Ohi[row0g * 2048 + colb] = hp0;
        *(uint32_t*)&Olo[row0g * 2048 + colb] = lp0;
        *(uint32_t*)&Ohi[(row0g + 8) * 2048 + colb] = hp1;
        *(uint32_t*)&Olo[(row0g + 8) * 2048 + colb] = lp1;
    }
}

// ---------------------------------------------------------------------------
extern "C" void kernel_launch(void* const* d_in, const int* in_sizes, int n_in,
                              void* d_out, int out_size)
{
    const float* residual = (const float*)d_in[0];
    const float* W_Q = (const float*)d_in[1];
    const float* W_K = (const float*)d_in[2];
    const float* W_V = (const float*)d_in[3];
    const float* W_O = (const float*)d_in[4];
    const int* sp = (const int*)d_in[5];

    float* out = (float*)d_out;
    float* k_cache = out + (size_t)B_ * S_ * D_;
    float* v_cache = k_cache + (size_t)B_ * S_ * KVH_ * DH_;

    float* qkv_ptr;
    __half *Ahi, *Alo, *Whi, *WOhi, *Phi, *Plo, *Khi, *Vhi;
    cudaGetSymbolAddress((void**)&qkv_ptr, g_qkv);
    cudaGetSymbolAddress((void**)&Ahi, g_Ahi);
    cudaGetSymbolAddress((void**)&Alo, g_Alo);
    cudaGetSymbolAddress((void**)&Whi, g_Whi);
    cudaGetSymbolAddress((void**)&WOhi, g_WOhi);
    cudaGetSymbolAddress((void**)&Phi, g_Phi);
    cudaGetSymbolAddress((void**)&Plo, g_Plo);
    cudaGetSymbolAddress((void**)&Khi, g_Khi);
    cudaGetSymbolAddress((void**)&Vhi, g_Vhi);

    cudaFuncSetAttribute(hmma_gemm, cudaFuncAttributeMaxDynamicSharedMemorySize,
                         GEMM_SMEM);
    cudaFuncSetAttribute(attn_mma_kernel, cudaFuncAttributeMaxDynamicSharedMemorySize,
                         ATT2_SMEM);

    // 0) splits / converts
    split_kernel<<<(M_ * D_ / 4 + 255) / 256, 256>>>(residual, Ahi, Alo, M_ * D_ / 4);
    cvt_kernel<<<(2048 * 2048 / 4 + 255) / 256, 256>>>(W_Q, Whi, 2048 * 2048 / 4);
    cvt_kernel<<<(512 * 2048 / 4 + 255) / 256, 256>>>(
        W_K, Whi + (size_t)2048 * 2048, 512 * 2048 / 4);
    cvt_kernel<<<(512 * 2048 / 4 + 255) / 256, 256>>>(
        W_V, Whi + (size_t)2560 * 2048, 512 * 2048 / 4);
    transpose_cvt_wo<<<dim3(64, 64), 256>>>(W_O, WOhi);

    // 1) fused QKV projection (fp16 2-pass)
    hmma_gemm<<<dim3(NQKV / 128, M_ / 128), 256, GEMM_SMEM>>>(
        Ahi, Alo, Whi, qkv_ptr, NQKV);

    // 2) RoPE + split producer (reuses Ahi/Alo as Qhi/Qlo)
    rope_split_kernel<<<M_, 256>>>(qkv_ptr, k_cache, v_cache,
                                   Ahi, Alo, Khi, Vhi, sp);

    // 3) tensor-core attention -> fp16 hi/lo output (Phi/Plo)
    attn_mma_kernel<<<dim3(S_ / 64, B_ * H_), 128, ATT2_SMEM>>>(
        Ahi, Alo, Khi, Vhi, Phi, Plo, sp);

    // 4) output projection (fp16 2-pass)
    hmma_gemm<<<dim3(D_ / 128, M_ / 128), 256, GEMM_SMEM>>>(
        Phi, Plo, WOhi, out, D_);
}

// round 8
// speedup vs baseline: 1.6805x; 1.1246x over previous
#include <cuda_runtime.h>
#include <cuda_fp16.h>
#include <math.h>
#include <stdint.h>

// Problem constants (fixed shapes from setup_inputs)
#define B_   2
#define S_   2048
#define D_   2048
#define H_   16
#define KVH_ 4
#define DH_  128
#define M_   (B_ * S_)          // 4096
#define NQKV 3072               // 2048 q + 512 k + 512 v

// Scratch (static device arrays; no runtime allocation allowed)
__device__ float g_qkv[M_ * NQKV];
__device__ __half g_Ahi[M_ * D_];     // residual hi; reused as Q hi after rope
__device__ __half g_Alo[M_ * D_];     // residual lo
__device__ __half g_Whi[NQKV * D_];   // W_Q|W_K|W_V rows, fp16
__device__ __half g_WOhi[D_ * D_];    // W_O transposed [d][he], fp16
__device__ __half g_Phi[M_ * D_];     // attention output hi
__device__ __half g_Plo[M_ * D_];     // attention output lo
__device__ __half g_Khi[M_ * 512];
__device__ __half g_Vhi[M_ * 512];

// ---------------------------------------------------------------------------
// helpers
// ---------------------------------------------------------------------------
__device__ __forceinline__ uint32_t smem_u32(const void* p) {
    uint32_t a;
    asm("{ .reg .u64 t; cvta.to.shared.u64 t, %1; cvt.u32.u64 %0, t; }"
        : "=r"(a) : "l"(p));
    return a;
}

__device__ __forceinline__ void cp16(uint32_t dst, const void* src) {
    asm volatile("cp.async.cg.shared.global [%0], [%1], 16;"
                 :: "r"(dst), "l"(src));
}

__device__ __forceinline__ void ldm_x4(uint32_t* r, uint32_t addr) {
    asm volatile("ldmatrix.sync.aligned.m8n8.x4.shared.b16 {%0,%1,%2,%3}, [%4];"
                 : "=r"(r[0]), "=r"(r[1]), "=r"(r[2]), "=r"(r[3]) : "r"(addr));
}

__device__ __forceinline__ void ldm_x4_t(uint32_t* r, uint32_t addr) {
    asm volatile("ldmatrix.sync.aligned.m8n8.x4.trans.shared.b16 {%0,%1,%2,%3}, [%4];"
                 : "=r"(r[0]), "=r"(r[1]), "=r"(r[2]), "=r"(r[3]) : "r"(addr));
}

__device__ __forceinline__ void mma_f16(float* c, const uint32_t* a,
                                        uint32_t b0, uint32_t b1) {
    asm volatile(
        "mma.sync.aligned.m16n8k16.row.col.f32.f16.f16.f32 "
        "{%0,%1,%2,%3}, {%4,%5,%6,%7}, {%8,%9}, {%0,%1,%2,%3};"
        : "+f"(c[0]), "+f"(c[1]), "+f"(c[2]), "+f"(c[3])
        : "r"(a[0]), "r"(a[1]), "r"(a[2]), "r"(a[3]), "r"(b0), "r"(b1));
}

// swizzled byte offset for a 16B segment (row r, seg s) in a [rows][32]fp16 block
__device__ __forceinline__ uint32_t swz_off(int r, int s) {
    return (uint32_t)(r * 64 + ((s ^ ((r >> 1) & 3)) * 16));
}

// swizzled byte offset for [rows][128 fp16] tiles (256B rows, 16 segs)
__device__ __forceinline__ uint32_t aswz(int r, int sg) {
    return (uint32_t)(r * 256 + ((sg ^ (r & 7)) * 16));
}

__device__ __forceinline__ uint32_t pack_hi2(float x0, float x1, float& r0, float& r1) {
    __half h0 = __float2half_rn(x0);
    __half h1 = __float2half_rn(x1);
    r0 = x0 - __half2float(h0);
    r1 = x1 - __half2float(h1);
    __half2 p = __halves2half2(h0, h1);
    return *(uint32_t*)&p;
}

__device__ __forceinline__ uint32_t pack_f2h2(float x0, float x1) {
    __half2 p = __floats2half2_rn(x0, x1);
    return *(uint32_t*)&p;
}

// ---------------------------------------------------------------------------
// HMMA GEMM: C[m,n] = sum_k A[m,k]*B[n,k], fp32 via fp16 2-pass (ah*bh + al*bh)
// CTA tile 128x128, 8 warps (4m x 2n), warp tile 32x64. K-chunk 32.
// stage = Ah|Al|Bh, each [128][32]fp16 (8KB) = 24KB; 3 stages = 72KB. 2 CTA/SM.
// ---------------------------------------------------------------------------
#define GEMM_STAGE 24576
#define GEMM_SMEM (3 * GEMM_STAGE)

__global__ __launch_bounds__(256, 2) void hmma_gemm(
    const __half* __restrict__ Ah, const __half* __restrict__ Al,
    const __half* __restrict__ Bh,
    float* __restrict__ C, int ldc)
{
    extern __shared__ char smem[];
    uint32_t sb = smem_u32(smem);

    int tid = threadIdx.x;
    int lane = tid & 31;
    int warp = tid >> 5;
    int warp_m = warp & 3;
    int warp_n = warp >> 2;
    int m0 = blockIdx.y * 128;
    int n0 = blockIdx.x * 128;

    int q = lane >> 3;
    int lrow = lane & 7;
    int arow_l = (q & 1) * 8 + lrow;
    int ksel = q >> 1;

    float acc[2][8][4];
#pragma unroll
    for (int i = 0; i < 2; i++)
#pragma unroll
        for (int j = 0; j < 8; j++)
#pragma unroll
            for (int k = 0; k < 4; k++) acc[i][j][k] = 0.f;

    auto load_chunk = [&](int c) {
        int k0 = c * 32;
        uint32_t buf = sb + (uint32_t)(c % 3) * GEMM_STAGE;
#pragma unroll
        for (int t = 0; t < 6; t++) {
            int g = tid + t * 256;           // 0..1535
            int mat = g >> 9;                // 0 Ah, 1 Al, 2 Bh
            int inner = g & 511;
            int r = inner >> 2;
            int s = inner & 3;
            const __half* base = (mat == 0) ? Ah : (mat == 1) ? Al : Bh;
            int row = ((mat < 2) ? m0 : n0) + r;
            const void* src = base + (size_t)row * 2048 + k0 + s * 8;
            cp16(buf + (uint32_t)mat * 8192u + swz_off(r, s), src);
        }
        asm volatile("cp.async.commit_group;" ::: "memory");
    };

    load_chunk(0);
    load_chunk(1);
    load_chunk(2);

    for (int c = 0; c < 64; c++) {
        asm volatile("cp.async.wait_group 2;" ::: "memory");
        __syncthreads();

        uint32_t buf = sb + (uint32_t)(c % 3) * GEMM_STAGE;
        uint32_t bAh = buf, bAl = buf + 8192, bBh = buf + 16384;

#pragma unroll
        for (int ks = 0; ks < 2; ks++) {
            int s = ks * 2 + ksel;
            uint32_t ah[2][4], al[2][4];
#pragma unroll
            for (int mi = 0; mi < 2; mi++) {
                int r = warp_m * 32 + mi * 16 + arow_l;
                ldm_x4(ah[mi], bAh + swz_off(r, s));
                ldm_x4(al[mi], bAl + swz_off(r, s));
            }
            uint32_t bh[8][2];
#pragma unroll
            for (int j = 0; j < 4; j++) {
                int r = warp_n * 64 + j * 16 + arow_l;
                uint32_t t4[4];
                ldm_x4(t4, bBh + swz_off(r, s));
                bh[j * 2 + 0][0] = t4[0]; bh[j * 2 + 0][1] = t4[2];
                bh[j * 2 + 1][0] = t4[1]; bh[j * 2 + 1][1] = t4[3];
            }
#pragma unroll
            for (int mi = 0; mi < 2; mi++) {
#pragma unroll
                for (int nj = 0; nj < 8; nj++) {
                    mma_f16(acc[mi][nj], ah[mi], bh[nj][0], bh[nj][1]);
                    mma_f16(acc[mi][nj], al[mi], bh[nj][0], bh[nj][1]);
                }
            }
        }
        __syncthreads();
        if (c + 3 < 64) load_chunk(c + 3);
        else asm volatile("cp.async.commit_group;" ::: "memory");
    }

    int rr = lane >> 2;
    int cc = (lane & 3) * 2;
#pragma unroll
    for (int mi = 0; mi < 2; mi++) {
        int r1 = m0 + warp_m * 32 + mi * 16 + rr;
#pragma unroll
        for (int nj = 0; nj < 8; nj++) {
            int col = n0 + warp_n * 64 + nj * 8 + cc;
            float2 v0 = make_float2(acc[mi][nj][0], acc[mi][nj][1]);
            float2 v1 = make_float2(acc[mi][nj][2], acc[mi][nj][3]);
            *(float2*)&C[(size_t)r1 * ldc + col] = v0;
            *(float2*)&C[(size_t)(r1 + 8) * ldc + col] = v1;
        }
    }
}

// ---------------------------------------------------------------------------
// Elementwise fp32 -> (fp16 hi, fp16 lo) split
// ---------------------------------------------------------------------------
__global__ __launch_bounds__(256) void split_kernel(
    const float* __restrict__ src, __half* __restrict__ hi,
    __half* __restrict__ lo, int n4)
{
    int i = blockIdx.x * 256 + threadIdx.x;
    if (i >= n4) return;
    float4 v = ((const float4*)src)[i];
    __half h0 = __float2half_rn(v.x);
    __half h1 = __float2half_rn(v.y);
    __half h2 = __float2half_rn(v.z);
    __half h3 = __float2half_rn(v.w);
    __half l0 = __float2half_rn(v.x - __half2float(h0));
    __half l1 = __float2half_rn(v.y - __half2float(h1));
    __half l2 = __float2half_rn(v.z - __half2float(h2));
    __half l3 = __float2half_rn(v.w - __half2float(h3));
    ushort4 hv = make_ushort4(__half_as_ushort(h0), __half_as_ushort(h1),
                              __half_as_ushort(h2), __half_as_ushort(h3));
    ushort4 lv = make_ushort4(__half_as_ushort(l0), __half_as_ushort(l1),
                              __half_as_ushort(l2), __half_as_ushort(l3));
    ((ushort4*)hi)[i] = hv;
    ((ushort4*)lo)[i] = lv;
}

// ---------------------------------------------------------------------------
// Elementwise fp32 -> fp16 (hi only) for weights
// ---------------------------------------------------------------------------
__global__ __launch_bounds__(256) void cvt_kernel(
    const float* __restrict__ src, __half* __restrict__ dst, int n4)
{
    int i = blockIdx.x * 256 + threadIdx.x;
    if (i >= n4) return;
    float4 v = ((const float4*)src)[i];
    ushort4 hv = make_ushort4(
        __half_as_ushort(__float2half_rn(v.x)),
        __half_as_ushort(__float2half_rn(v.y)),
        __half_as_ushort(__float2half_rn(v.z)),
        __half_as_ushort(__float2half_rn(v.w)));
    ((ushort4*)dst)[i] = hv;
}

// ---------------------------------------------------------------------------
// Transpose + convert W_O: in [he=2048][d=2048] fp32 -> out [d][he] fp16
// ---------------------------------------------------------------------------
__global__ __launch_bounds__(256) void transpose_cvt_wo(
    const float* __restrict__ W, __half* __restrict__ Th)
{
    __shared__ float t[32][33];
    int bx = blockIdx.x * 32;
    int by = blockIdx.y * 32;
    int x = threadIdx.x & 31;
    int y0 = threadIdx.x >> 5;
#pragma unroll
    for (int i = 0; i < 32; i += 8)
        t[y0 + i][x] = W[(size_t)(by + y0 + i) * 2048 + bx + x];
    __syncthreads();
#pragma unroll
    for (int i = 0; i < 32; i += 8) {
        float v = t[x][y0 + i];
        Th[(size_t)(bx + y0 + i) * 2048 + by + x] = __float2half_rn(v);
    }
}

// ---------------------------------------------------------------------------
// RoPE producer:
//  q: rope, scale 1/sqrt(Dh) -> fp16 Qhi (no lo; attention is 1-pass now)
//  k: rope -> fp32 k_cache + fp16 Khi
//  v: copy -> fp32 v_cache + fp16 Vhi
// ---------------------------------------------------------------------------
__global__ __launch_bounds__(256) void rope_split_kernel(
    const float* __restrict__ qkv,
    float* __restrict__ kc, float* __restrict__ vc,
    __half* __restrict__ Qhi,
    __half* __restrict__ Khi, __half* __restrict__ Vhi,
    const int* __restrict__ sp_ptr)
{
    const float LOG2_BASE_OVER_HALF = 13.287712379549449f / 64.0f;
    const float scale = 0.08838834764831845f;  // 1/sqrt(128)
    int m = blockIdx.x;
    int s = m & (S_ - 1);
    int sp = *sp_ptr;
    float pos = (float)(sp + s);
    int tid = threadIdx.x;

    for (int p = tid; p < H_ * 64; p += 256) {
        int h = p >> 6, e = p & 63;
        float inv = exp2f(-(float)e * LOG2_BASE_OVER_HALF);
        float ang = pos * inv;
        float sn, cs;
        sincosf(ang, &sn, &cs);
        const float* base = qkv + (size_t)m * NQKV + h * DH_;
        float x1 = base[e], x2 = base[e + 64];
        float y1 = (x1 * cs - x2 * sn) * scale;
        float y2 = (x1 * sn + x2 * cs) * scale;
        size_t o = (size_t)m * D_ + h * DH_;
        Qhi[o + e]      = __float2half_rn(y1);
        Qhi[o + e + 64] = __float2half_rn(y2);
    }
    for (int p = tid; p < KVH_ * 64; p += 256) {
        int h = p >> 6, e = p & 63;
        float inv = exp2f(-(float)e * LOG2_BASE_OVER_HALF);
        float ang = pos * inv;
        float sn, cs;
        sincosf(ang, &sn, &cs);
        const float* base = qkv + (size_t)m * NQKV + 2048 + h * DH_;
        float x1 = base[e], x2 = base[e + 64];
        float y1 = x1 * cs - x2 * sn;
        float y2 = x1 * sn + x2 * cs;
        size_t o = (size_t)m * (KVH_ * DH_) + h * DH_;
        kc[o + e]      = y1;
        kc[o + e + 64] = y2;
        Khi[o + e]      = __float2half_rn(y1);
        Khi[o + e + 64] = __float2half_rn(y2);
    }
    for (int i = tid; i < KVH_ * DH_; i += 256) {
        float v = qkv[(size_t)m * NQKV + 2560 + i];
        size_t o = (size_t)m * (KVH_ * DH_) + i;
        vc[o] = v;
        Vhi[o] = __float2half_rn(v);
    }
}

// ---------------------------------------------------------------------------
// Tensor-core flash attention, pure fp16 single-pass (fp32 accumulate).
// BM=64 (4 warps x m16), BN=64, Dh=128. Q frags hoisted to registers.
// KV stage = Khi|Vhi each 64x128 fp16 (16KB) = 32KB; 2 stages.
// smem: Q 16KB + 64KB = 80KB -> 2 CTAs/SM.
// Output: O split to fp16 hi/lo (out-projection stays 2-pass).
// ---------------------------------------------------------------------------
#define ATT_KV_STAGE 32768
#define ATT2_SMEM (16384 + 2 * ATT_KV_STAGE)

__global__ __launch_bounds__(128, 2) void attn_mma_kernel(
    const __half* __restrict__ Qhi,
    const __half* __restrict__ Khi, const __half* __restrict__ Vhi,
    __half* __restrict__ Ohi, __half* __restrict__ Olo,
    const int* __restrict__ sp_ptr)
{
    extern __shared__ char smem[];
    uint32_t sb = smem_u32(smem);
    const uint32_t sQh = sb;
    const uint32_t sKV = sb + 16384;

    int tid = threadIdx.x;
    int lane = tid & 31;
    int warp = tid >> 5;                 // 0..3
    int bh = blockIdx.y;
    int b = bh >> 4, h = bh & 15, kvh = h >> 2;
    int q0 = blockIdx.x * 64;
    int sp = *sp_ptr;
    float slope = exp2f(-0.5f * (float)(h + 1));

    int fr = ((lane >> 3) & 1) * 8 + (lane & 7);
    int fs = lane >> 4;

    int kt_end = (sp + q0 + 63) >> 6;
    if (kt_end > S_ / 64 - 1) kt_end = S_ / 64 - 1;

    // ---- KV tile loader (Khi + Vhi, 64 rows x 128 cols each) ----
    auto load_kv = [&](int kt) {
        int k0 = (kt <= kt_end ? kt : kt_end) * 64;
        uint32_t stage = sKV + (uint32_t)(kt & 1) * ATT_KV_STAGE;
#pragma unroll
        for (int i = 0; i < 16; i++) {
            int idx = tid + i * 128;   // 0..2047
            int t = idx >> 10;         // 0 Khi, 1 Vhi
            int inner = idx & 1023;
            int r = inner >> 4, sg = inner & 15;
            const __half* basep = t ? Vhi : Khi;
            const __half* src =
                basep + (size_t)(b * S_ + k0 + r) * 512 + kvh * 128 + sg * 8;
            cp16(stage + (uint32_t)t * 16384u + aswz(r, sg), src);
        }
        asm volatile("cp.async.commit_group;" ::: "memory");
    };

    // ---- prologue: Q (group 0), KV(0) (group 1), KV(1) (group 2) ----
#pragma unroll
    for (int i = 0; i < 8; i++) {
        int idx = tid + i * 128;          // 0..1023
        int r = idx >> 4, sg = idx & 15;
        const __half* src = Qhi
            + (size_t)(b * S_ + q0 + r) * 2048 + h * 128 + sg * 8;
        cp16(sQh + aswz(r, sg), src);
    }
    asm volatile("cp.async.commit_group;" ::: "memory");
    load_kv(0);
    load_kv(1);

    // ---- Q fragments -> registers (kt-invariant) ----
    asm volatile("cp.async.wait_group 2;" ::: "memory");
    __syncthreads();
    uint32_t qh[8][4];
#pragma unroll
    for (int s = 0; s < 8; s++)
        ldm_x4(qh[s], sQh + aswz(warp * 16 + fr, 2 * s + fs));

    float Oacc[16][4];
#pragma unroll
    for (int e = 0; e < 16; e++)
#pragma unroll
        for (int k = 0; k < 4; k++) Oacc[e][k] = 0.f;
    float m0r = -1e30f, m1r = -1e30f;
    float l0r = 0.f, l1r = 0.f;

    int row0 = q0 + warp * 16 + (lane >> 2);
    int qp0 = sp + row0, qp1 = qp0 + 8;

    for (int kt = 0; kt <= kt_end; kt++) {
        int k0 = kt * 64;
        asm volatile("cp.async.wait_group 1;" ::: "memory");
        __syncthreads();

        uint32_t stage = sKV + (uint32_t)(kt & 1) * ATT_KV_STAGE;
        uint32_t sKh = stage, sVh = stage + 16384;

        // ---- S = Q K^T (single pass fp16) ----
        float sacc[8][4];
#pragma unroll
        for (int nj = 0; nj < 8; nj++)
#pragma unroll
            for (int k = 0; k < 4; k++) sacc[nj][k] = 0.f;

#pragma unroll
        for (int s = 0; s < 8; s++) {
            uint32_t kbh[8][2], t4[4];
#pragma unroll
            for (int j = 0; j < 4; j++) {
                ldm_x4(t4, sKh + aswz(j * 16 + fr, 2 * s + fs));
                kbh[2 * j][0] = t4[0]; kbh[2 * j][1] = t4[2];
                kbh[2 * j + 1][0] = t4[1]; kbh[2 * j + 1][1] = t4[3];
            }
#pragma unroll
            for (int nj = 0; nj < 8; nj++)
                mma_f16(sacc[nj], qh[s], kbh[nj][0], kbh[nj][1]);
        }

        // ---- bias + causal mask ----
#pragma unroll
        for (int nj = 0; nj < 8; nj++) {
            int c = k0 + nj * 8 + (lane & 3) * 2;
            sacc[nj][0] = (c     <= qp0) ? sacc[nj][0] - slope * (float)(qp0 - c)     : -1e30f;
            sacc[nj][1] = (c + 1 <= qp0) ? sacc[nj][1] - slope * (float)(qp0 - c - 1) : -1e30f;
            sacc[nj][2] = (c     <= qp1) ? sacc[nj][2] - slope * (float)(qp1 - c)     : -1e30f;
            sacc[nj][3] = (c + 1 <= qp1) ? sacc[nj][3] - slope * (float)(qp1 - c - 1) : -1e30f;
        }

        // ---- online softmax ----
        float mx0 = -1e30f, mx1 = -1e30f;
#pragma unroll
        for (int nj = 0; nj < 8; nj++) {
            mx0 = fmaxf(mx0, fmaxf(sacc[nj][0], sacc[nj][1]));
            mx1 = fmaxf(mx1, fmaxf(sacc[nj][2], sacc[nj][3]));
        }
        mx0 = fmaxf(mx0, __shfl_xor_sync(0xffffffffu, mx0, 1));
        mx0 = fmaxf(mx0, __shfl_xor_sync(0xffffffffu, mx0, 2));
        mx1 = fmaxf(mx1, __shfl_xor_sync(0xffffffffu, mx1, 1));
        mx1 = fmaxf(mx1, __shfl_xor_sync(0xffffffffu, mx1, 2));
        float mn0 = fmaxf(m0r, mx0), mn1 = fmaxf(m1r, mx1);
        float corr0 = __expf(m0r - mn0), corr1 = __expf(m1r - mn1);
        m0r = mn0; m1r = mn1;

        float ls0 = 0.f, ls1 = 0.f;
#pragma unroll
        for (int nj = 0; nj < 8; nj++) {
            sacc[nj][0] = __expf(sacc[nj][0] - mn0);
            sacc[nj][1] = __expf(sacc[nj][1] - mn0);
            sacc[nj][2] = __expf(sacc[nj][2] - mn1);
            sacc[nj][3] = __expf(sacc[nj][3] - mn1);
            ls0 += sacc[nj][0] + sacc[nj][1];
            ls1 += sacc[nj][2] + sacc[nj][3];
        }
        ls0 += __shfl_xor_sync(0xffffffffu, ls0, 1);
        ls0 += __shfl_xor_sync(0xffffffffu, ls0, 2);
        ls1 += __shfl_xor_sync(0xffffffffu, ls1, 1);
        ls1 += __shfl_xor_sync(0xffffffffu, ls1, 2);
        l0r = l0r * corr0 + ls0;
        l1r = l1r * corr1 + ls1;

#pragma unroll
        for (int e = 0; e < 16; e++) {
            Oacc[e][0] *= corr0; Oacc[e][1] *= corr0;
            Oacc[e][2] *= corr1; Oacc[e][3] *= corr1;
        }

        // ---- P -> fp16 A-fragments (4 k16 tiles, single pass) ----
        uint32_t phi[4][4];
#pragma unroll
        for (int t = 0; t < 4; t++) {
            phi[t][0] = pack_f2h2(sacc[2 * t][0], sacc[2 * t][1]);
            phi[t][1] = pack_f2h2(sacc[2 * t][2], sacc[2 * t][3]);
            phi[t][2] = pack_f2h2(sacc[2 * t + 1][0], sacc[2 * t + 1][1]);
            phi[t][3] = pack_f2h2(sacc[2 * t + 1][2], sacc[2 * t + 1][3]);
        }

        // ---- O += P V (single pass fp16) ----
#pragma unroll
        for (int t = 0; t < 4; t++) {
#pragma unroll
            for (int u = 0; u < 8; u++) {
                uint32_t th[4];
                ldm_x4_t(th, sVh + aswz(t * 16 + fr, 2 * u + fs));
                mma_f16(Oacc[2 * u], phi[t], th[0], th[1]);
                mma_f16(Oacc[2 * u + 1], phi[t], th[2], th[3]);
            }
        }
        __syncthreads();
        if (kt + 2 <= kt_end) load_kv(kt + 2);
        else asm volatile("cp.async.commit_group;" ::: "memory");
    }

    // ---- epilogue: normalize + split to fp16 hi/lo (for 2-pass out-proj) ----
    float inv0 = 1.f / l0r, inv1 = 1.f / l1r;
    size_t row0g = (size_t)(b * S_ + row0);
#pragma unroll
    for (int e = 0; e < 16; e++) {
        int colb = h * 128 + e * 8 + (lane & 3) * 2;
        float x0 = Oacc[e][0] * inv0, x1 = Oacc[e][1] * inv0;
        float x2 = Oacc[e][2] * inv1, x3 = Oacc[e][3] * inv1;
        float r0, r1;
        uint32_t hp0 = pack_hi2(x0, x1, r0, r1);
        uint32_t lp0 = pack_f2h2(r0, r1);
        uint32_t hp1 = pack_hi2(x2, x3, r0, r1);
        uint32_t lp1 = pack_f2h2(r0, r1);
        *(uint32_t*)&Ohi[row0g * 2048 + colb] = hp0;
        *(uint32_t*)&Olo[row0g * 2048 + colb] = lp0;
        *(uint32_t*)&Ohi[(row0g + 8) * 2048 + colb] = hp1;
        *(uint32_t*)&Olo[(row0g + 8) * 2048 + colb] = lp1;
    }
}

// ---------------------------------------------------------------------------
extern "C" void kernel_launch(void* const* d_in, const int* in_sizes, int n_in,
                              void* d_out, int out_size)
{
    const float* residual = (const float*)d_in[0];
    const float* W_Q = (const float*)d_in[1];
    const float* W_K = (const float*)d_in[2];
    const float* W_V = (const float*)d_in[3];
    const float* W_O = (const float*)d_in[4];
    const int* sp = (const int*)d_in[5];

    float* out = (float*)d_out;
    float* k_cache = out + (size_t)B_ * S_ * D_;
    float* v_cache = k_cache + (size_t)B_ * S_ * KVH_ * DH_;

    float* qkv_ptr;
    __half *Ahi, *Alo, *Whi, *WOhi, *Phi, *Plo, *Khi, *Vhi;
    cudaGetSymbolAddress((void**)&qkv_ptr, g_qkv);
    cudaGetSymbolAddress((void**)&Ahi, g_Ahi);
    cudaGetSymbolAddress((void**)&Alo, g_Alo);
    cudaGetSymbolAddress((void**)&Whi, g_Whi);
    cudaGetSymbolAddress((void**)&WOhi, g_WOhi);
    cudaGetSymbolAddress((void**)&Phi, g_Phi);
    cudaGetSymbolAddress((void**)&Plo, g_Plo);
    cudaGetSymbolAddress((void**)&Khi, g_Khi);
    cudaGetSymbolAddress((void**)&Vhi, g_Vhi);

    cudaFuncSetAttribute(hmma_gemm, cudaFuncAttributeMaxDynamicSharedMemorySize,
                         GEMM_SMEM);
    cudaFuncSetAttribute(attn_mma_kernel, cudaFuncAttributeMaxDynamicSharedMemorySize,
                         ATT2_SMEM);

    // 0) splits / converts
    split_kernel<<<(M_ * D_ / 4 + 255) / 256, 256>>>(residual, Ahi, Alo, M_ * D_ / 4);
    cvt_kernel<<<(2048 * 2048 / 4 + 255) / 256, 256>>>(W_Q, Whi, 2048 * 2048 / 4);
    cvt_kernel<<<(512 * 2048 / 4 + 255) / 256, 256>>>(
        W_K, Whi + (size_t)2048 * 2048, 512 * 2048 / 4);
    cvt_kernel<<<(512 * 2048 / 4 + 255) / 256, 256>>>(
        W_V, Whi + (size_t)2560 * 2048, 512 * 2048 / 4);
    transpose_cvt_wo<<<dim3(64, 64), 256>>>(W_O, WOhi);

    // 1) fused QKV projection (fp16 2-pass)
    hmma_gemm<<<dim3(NQKV / 128, M_ / 128), 256, GEMM_SMEM>>>(
        Ahi, Alo, Whi, qkv_ptr, NQKV);

    // 2) RoPE producer (Qhi reuses g_Ahi)
    rope_split_kernel<<<M_, 256>>>(qkv_ptr, k_cache, v_cache,
                                   Ahi, Khi, Vhi, sp);

    // 3) tensor-core attention (fp16 1-pass) -> fp16 hi/lo output
    attn_mma_kernel<<<dim3(S_ / 64, B_ * H_), 128, ATT2_SMEM>>>(
        Ahi, Khi, Vhi, Phi, Plo, sp);

    // 4) output projection (fp16 2-pass)
    hmma_gemm<<<dim3(D_ / 128, M_ / 128), 256, GEMM_SMEM>>>(
        Phi, Plo, WOhi, out, D_);
}

// round 9
// speedup vs baseline: 2.5615x; 1.5242x over previous
#include <cuda_runtime.h>
#include <cuda_fp16.h>
#include <math.h>
#include <stdint.h>

// Problem constants (fixed shapes from setup_inputs)
#define B_   2
#define S_   2048
#define D_   2048
#define H_   16
#define KVH_ 4
#define DH_  128
#define M_   (B_ * S_)          // 4096
#define NQKV 3072               // 2048 q + 512 k + 512 v

// Scratch (static device arrays; no runtime allocation allowed)
__device__ float g_qkv[M_ * NQKV];
__device__ __half g_Ahi[M_ * D_];     // residual fp16; reused as Q after rope
__device__ __half g_Whi[NQKV * D_];   // W_Q|W_K|W_V rows, fp16
__device__ __half g_WOhi[D_ * D_];    // W_O transposed [d][he], fp16
__device__ __half g_Phi[M_ * D_];     // attention output fp16
__device__ __half g_Khi[M_ * 512];
__device__ __half g_Vhi[M_ * 512];

// ---------------------------------------------------------------------------
// helpers
// ---------------------------------------------------------------------------
__device__ __forceinline__ uint32_t smem_u32(const void* p) {
    uint32_t a;
    asm("{ .reg .u64 t; cvta.to.shared.u64 t, %1; cvt.u32.u64 %0, t; }"
        : "=r"(a) : "l"(p));
    return a;
}

__device__ __forceinline__ void cp16(uint32_t dst, const void* src) {
    asm volatile("cp.async.cg.shared.global [%0], [%1], 16;"
                 :: "r"(dst), "l"(src));
}

__device__ __forceinline__ void ldm_x4(uint32_t* r, uint32_t addr) {
    asm volatile("ldmatrix.sync.aligned.m8n8.x4.shared.b16 {%0,%1,%2,%3}, [%4];"
                 : "=r"(r[0]), "=r"(r[1]), "=r"(r[2]), "=r"(r[3]) : "r"(addr));
}

__device__ __forceinline__ void ldm_x4_t(uint32_t* r, uint32_t addr) {
    asm volatile("ldmatrix.sync.aligned.m8n8.x4.trans.shared.b16 {%0,%1,%2,%3}, [%4];"
                 : "=r"(r[0]), "=r"(r[1]), "=r"(r[2]), "=r"(r[3]) : "r"(addr));
}

__device__ __forceinline__ void mma_f16(float* c, const uint32_t* a,
                                        uint32_t b0, uint32_t b1) {
    asm volatile(
        "mma.sync.aligned.m16n8k16.row.col.f32.f16.f16.f32 "
        "{%0,%1,%2,%3}, {%4,%5,%6,%7}, {%8,%9}, {%0,%1,%2,%3};"
        : "+f"(c[0]), "+f"(c[1]), "+f"(c[2]), "+f"(c[3])
        : "r"(a[0]), "r"(a[1]), "r"(a[2]), "r"(a[3]), "r"(b0), "r"(b1));
}

// swizzled byte offset for a 16B segment (row r, seg s) in a [rows][32]fp16 block
__device__ __forceinline__ uint32_t swz_off(int r, int s) {
    return (uint32_t)(r * 64 + ((s ^ ((r >> 1) & 3)) * 16));
}

// swizzled byte offset for [rows][128 fp16] tiles (256B rows, 16 segs)
__device__ __forceinline__ uint32_t aswz(int r, int sg) {
    return (uint32_t)(r * 256 + ((sg ^ (r & 7)) * 16));
}

__device__ __forceinline__ uint32_t pack_f2h2(float x0, float x1) {
    __half2 p = __floats2half2_rn(x0, x1);
    return *(uint32_t*)&p;
}

// ---------------------------------------------------------------------------
// HMMA GEMM: C[m,n] = sum_k A[m,k]*B[n,k], single-pass fp16, fp32 accumulate.
// CTA tile 128x128, 8 warps (4m x 2n), warp tile 32x64. K-chunk 32.
// stage = Ah|Bh, each [128][32]fp16 (8KB) = 16KB; 4 stages = 64KB. 2 CTA/SM.
// ---------------------------------------------------------------------------
#define GEMM_STAGE 16384
#define GEMM_SMEM (4 * GEMM_STAGE)

__global__ __launch_bounds__(256, 2) void hmma_gemm(
    const __half* __restrict__ Ah, const __half* __restrict__ Bh,
    float* __restrict__ C, int ldc)
{
    extern __shared__ char smem[];
    uint32_t sb = smem_u32(smem);

    int tid = threadIdx.x;
    int lane = tid & 31;
    int warp = tid >> 5;
    int warp_m = warp & 3;
    int warp_n = warp >> 2;
    int m0 = blockIdx.y * 128;
    int n0 = blockIdx.x * 128;

    int q = lane >> 3;
    int lrow = lane & 7;
    int arow_l = (q & 1) * 8 + lrow;
    int ksel = q >> 1;

    float acc[2][8][4];
#pragma unroll
    for (int i = 0; i < 2; i++)
#pragma unroll
        for (int j = 0; j < 8; j++)
#pragma unroll
            for (int k = 0; k < 4; k++) acc[i][j][k] = 0.f;

    auto load_chunk = [&](int c) {
        int k0 = c * 32;
        uint32_t buf = sb + (uint32_t)(c & 3) * GEMM_STAGE;
#pragma unroll
        for (int t = 0; t < 4; t++) {
            int g = tid + t * 256;           // 0..1023
            int mat = g >> 9;                // 0 Ah, 1 Bh
            int inner = g & 511;
            int r = inner >> 2;
            int s = inner & 3;
            const __half* base = mat ? Bh : Ah;
            int row = (mat ? n0 : m0) + r;
            const void* src = base + (size_t)row * 2048 + k0 + s * 8;
            cp16(buf + (uint32_t)mat * 8192u + swz_off(r, s), src);
        }
        asm volatile("cp.async.commit_group;" ::: "memory");
    };

    load_chunk(0);
    load_chunk(1);
    load_chunk(2);
    load_chunk(3);

    for (int c = 0; c < 64; c++) {
        asm volatile("cp.async.wait_group 3;" ::: "memory");
        __syncthreads();

        uint32_t buf = sb + (uint32_t)(c & 3) * GEMM_STAGE;
        uint32_t bAh = buf, bBh = buf + 8192;

#pragma unroll
        for (int ks = 0; ks < 2; ks++) {
            int s = ks * 2 + ksel;
            uint32_t ah[2][4];
#pragma unroll
            for (int mi = 0; mi < 2; mi++) {
                int r = warp_m * 32 + mi * 16 + arow_l;
                ldm_x4(ah[mi], bAh + swz_off(r, s));
            }
            uint32_t bh[8][2];
#pragma unroll
            for (int j = 0; j < 4; j++) {
                int r = warp_n * 64 + j * 16 + arow_l;
                uint32_t t4[4];
                ldm_x4(t4, bBh + swz_off(r, s));
                bh[j * 2 + 0][0] = t4[0]; bh[j * 2 + 0][1] = t4[2];
                bh[j * 2 + 1][0] = t4[1]; bh[j * 2 + 1][1] = t4[3];
            }
#pragma unroll
            for (int mi = 0; mi < 2; mi++) {
#pragma unroll
                for (int nj = 0; nj < 8; nj++)
                    mma_f16(acc[mi][nj], ah[mi], bh[nj][0], bh[nj][1]);
            }
        }
        __syncthreads();
        if (c + 4 < 64) load_chunk(c + 4);
        else asm volatile("cp.async.commit_group;" ::: "memory");
    }

    int rr = lane >> 2;
    int cc = (lane & 3) * 2;
#pragma unroll
    for (int mi = 0; mi < 2; mi++) {
        int r1 = m0 + warp_m * 32 + mi * 16 + rr;
#pragma unroll
        for (int nj = 0; nj < 8; nj++) {
            int col = n0 + warp_n * 64 + nj * 8 + cc;
            float2 v0 = make_float2(acc[mi][nj][0], acc[mi][nj][1]);
            float2 v1 = make_float2(acc[mi][nj][2], acc[mi][nj][3]);
            *(float2*)&C[(size_t)r1 * ldc + col] = v0;
            *(float2*)&C[(size_t)(r1 + 8) * ldc + col] = v1;
        }
    }
}

// ---------------------------------------------------------------------------
// Elementwise fp32 -> fp16
// ---------------------------------------------------------------------------
__global__ __launch_bounds__(256) void cvt_kernel(
    const float* __restrict__ src, __half* __restrict__ dst, int n4)
{
    int i = blockIdx.x * 256 + threadIdx.x;
    if (i >= n4) return;
    float4 v = ((const float4*)src)[i];
    ushort4 hv = make_ushort4(
        __half_as_ushort(__float2half_rn(v.x)),
        __half_as_ushort(__float2half_rn(v.y)),
        __half_as_ushort(__float2half_rn(v.z)),
        __half_as_ushort(__float2half_rn(v.w)));
    ((ushort4*)dst)[i] = hv;
}

// ---------------------------------------------------------------------------
// Transpose + convert W_O: in [he=2048][d=2048] fp32 -> out [d][he] fp16
// ---------------------------------------------------------------------------
__global__ __launch_bounds__(256) void transpose_cvt_wo(
    const float* __restrict__ W, __half* __restrict__ Th)
{
    __shared__ float t[32][33];
    int bx = blockIdx.x * 32;
    int by = blockIdx.y * 32;
    int x = threadIdx.x & 31;
    int y0 = threadIdx.x >> 5;
#pragma unroll
    for (int i = 0; i < 32; i += 8)
        t[y0 + i][x] = W[(size_t)(by + y0 + i) * 2048 + bx + x];
    __syncthreads();
#pragma unroll
    for (int i = 0; i < 32; i += 8) {
        float v = t[x][y0 + i];
        Th[(size_t)(bx + y0 + i) * 2048 + by + x] = __float2half_rn(v);
    }
}

// ---------------------------------------------------------------------------
// RoPE producer:
//  q: rope, scale 1/sqrt(Dh) -> fp16 Qhi
//  k: rope -> fp32 k_cache + fp16 Khi
//  v: copy -> fp32 v_cache + fp16 Vhi
// ---------------------------------------------------------------------------
__global__ __launch_bounds__(256) void rope_split_kernel(
    const float* __restrict__ qkv,
    float* __restrict__ kc, float* __restrict__ vc,
    __half* __restrict__ Qhi,
    __half* __restrict__ Khi, __half* __restrict__ Vhi,
    const int* __restrict__ sp_ptr)
{
    const float LOG2_BASE_OVER_HALF = 13.287712379549449f / 64.0f;
    const float scale = 0.08838834764831845f;  // 1/sqrt(128)
    int m = blockIdx.x;
    int s = m & (S_ - 1);
    int sp = *sp_ptr;
    float pos = (float)(sp + s);
    int tid = threadIdx.x;

    for (int p = tid; p < H_ * 64; p += 256) {
        int h = p >> 6, e = p & 63;
        float inv = exp2f(-(float)e * LOG2_BASE_OVER_HALF);
        float ang = pos * inv;
        float sn, cs;
        sincosf(ang, &sn, &cs);
        const float* base = qkv + (size_t)m * NQKV + h * DH_;
        float x1 = base[e], x2 = base[e + 64];
        float y1 = (x1 * cs - x2 * sn) * scale;
        float y2 = (x1 * sn + x2 * cs) * scale;
        size_t o = (size_t)m * D_ + h * DH_;
        Qhi[o + e]      = __float2half_rn(y1);
        Qhi[o + e + 64] = __float2half_rn(y2);
    }
    for (int p = tid; p < KVH_ * 64; p += 256) {
        int h = p >> 6, e = p & 63;
        float inv = exp2f(-(float)e * LOG2_BASE_OVER_HALF);
        float ang = pos * inv;
        float sn, cs;
        sincosf(ang, &sn, &cs);
        const float* base = qkv + (size_t)m * NQKV + 2048 + h * DH_;
        float x1 = base[e], x2 = base[e + 64];
        float y1 = x1 * cs - x2 * sn;
        float y2 = x1 * sn + x2 * cs;
        size_t o = (size_t)m * (KVH_ * DH_) + h * DH_;
        kc[o + e]      = y1;
        kc[o + e + 64] = y2;
        Khi[o + e]      = __float2half_rn(y1);
        Khi[o + e + 64] = __float2half_rn(y2);
    }
    for (int i = tid; i < KVH_ * DH_; i += 256) {
        float v = qkv[(size_t)m * NQKV + 2560 + i];
        size_t o = (size_t)m * (KVH_ * DH_) + i;
        vc[o] = v;
        Vhi[o] = __float2half_rn(v);
    }
}

// ---------------------------------------------------------------------------
// Tensor-core flash attention, pure fp16 (fp32 accumulate).
// BM=64 (4 warps x m16), BN=64, Dh=128. Q frags hoisted to registers.
// KV stage = Khi|Vhi each 64x128 fp16 (16KB) = 32KB; 2 stages.
// smem: Q 16KB + 64KB = 80KB -> 2 CTAs/SM.
// ---------------------------------------------------------------------------
#define ATT_KV_STAGE 32768
#define ATT2_SMEM (16384 + 2 * ATT_KV_STAGE)

__global__ __launch_bounds__(128, 2) void attn_mma_kernel(
    const __half* __restrict__ Qhi,
    const __half* __restrict__ Khi, const __half* __restrict__ Vhi,
    __half* __restrict__ Ohi,
    const int* __restrict__ sp_ptr)
{
    extern __shared__ char smem[];
    uint32_t sb = smem_u32(smem);
    const uint32_t sQh = sb;
    const uint32_t sKV = sb + 16384;

    int tid = threadIdx.x;
    int lane = tid & 31;
    int warp = tid >> 5;                 // 0..3
    int bh = blockIdx.y;
    int b = bh >> 4, h = bh & 15, kvh = h >> 2;
    int q0 = blockIdx.x * 64;
    int sp = *sp_ptr;
    float slope = exp2f(-0.5f * (float)(h + 1));

    int fr = ((lane >> 3) & 1) * 8 + (lane & 7);
    int fs = lane >> 4;

    int kt_end = (sp + q0 + 63) >> 6;
    if (kt_end > S_ / 64 - 1) kt_end = S_ / 64 - 1;

    // ---- KV tile loader (Khi + Vhi, 64 rows x 128 cols each) ----
    auto load_kv = [&](int kt) {
        int k0 = (kt <= kt_end ? kt : kt_end) * 64;
        uint32_t stage = sKV + (uint32_t)(kt & 1) * ATT_KV_STAGE;
#pragma unroll
        for (int i = 0; i < 16; i++) {
            int idx = tid + i * 128;   // 0..2047
            int t = idx >> 10;         // 0 Khi, 1 Vhi
            int inner = idx & 1023;
            int r = inner >> 4, sg = inner & 15;
            const __half* basep = t ? Vhi : Khi;
            const __half* src =
                basep + (size_t)(b * S_ + k0 + r) * 512 + kvh * 128 + sg * 8;
            cp16(stage + (uint32_t)t * 16384u + aswz(r, sg), src);
        }
        asm volatile("cp.async.commit_group;" ::: "memory");
    };

    // ---- prologue: Q (group 0), KV(0) (group 1), KV(1) (group 2) ----
#pragma unroll
    for (int i = 0; i < 8; i++) {
        int idx = tid + i * 128;          // 0..1023
        int r = idx >> 4, sg = idx & 15;
        const __half* src = Qhi
            + (size_t)(b * S_ + q0 + r) * 2048 + h * 128 + sg * 8;
        cp16(sQh + aswz(r, sg), src);
    }
    asm volatile("cp.async.commit_group;" ::: "memory");
    load_kv(0);
    load_kv(1);

    // ---- Q fragments -> registers (kt-invariant) ----
    asm volatile("cp.async.wait_group 2;" ::: "memory");
    __syncthreads();
    uint32_t qh[8][4];
#pragma unroll
    for (int s = 0; s < 8; s++)
        ldm_x4(qh[s], sQh + aswz(warp * 16 + fr, 2 * s + fs));

    float Oacc[16][4];
#pragma unroll
    for (int e = 0; e < 16; e++)
#pragma unroll
        for (int k = 0; k < 4; k++) Oacc[e][k] = 0.f;
    float m0r = -1e30f, m1r = -1e30f;
    float l0r = 0.f, l1r = 0.f;

    int row0 = q0 + warp * 16 + (lane >> 2);
    int qp0 = sp + row0, qp1 = qp0 + 8;

    for (int kt = 0; kt <= kt_end; kt++) {
        int k0 = kt * 64;
        asm volatile("cp.async.wait_group 1;" ::: "memory");
        __syncthreads();

        uint32_t stage = sKV + (uint32_t)(kt & 1) * ATT_KV_STAGE;
        uint32_t sKh = stage, sVh = stage + 16384;

        // ---- S = Q K^T ----
        float sacc[8][4];
#pragma unroll
        for (int nj = 0; nj < 8; nj++)
#pragma unroll
            for (int k = 0; k < 4; k++) sacc[nj][k] = 0.f;

#pragma unroll
        for (int s = 0; s < 8; s++) {
            uint32_t kbh[8][2], t4[4];
#pragma unroll
            for (int j = 0; j < 4; j++) {
                ldm_x4(t4, sKh + aswz(j * 16 + fr, 2 * s + fs));
                kbh[2 * j][0] = t4[0]; kbh[2 * j][1] = t4[2];
                kbh[2 * j + 1][0] = t4[1]; kbh[2 * j + 1][1] = t4[3];
            }
#pragma unroll
            for (int nj = 0; nj < 8; nj++)
                mma_f16(sacc[nj], qh[s], kbh[nj][0], kbh[nj][1]);
        }

        // ---- bias + causal mask ----
#pragma unroll
        for (int nj = 0; nj < 8; nj++) {
            int c = k0 + nj * 8 + (lane & 3) * 2;
            sacc[nj][0] = (c     <= qp0) ? sacc[nj][0] - slope * (float)(qp0 - c)     : -1e30f;
            sacc[nj][1] = (c + 1 <= qp0) ? sacc[nj][1] - slope * (float)(qp0 - c - 1) : -1e30f;
            sacc[nj][2] = (c     <= qp1) ? sacc[nj][2] - slope * (float)(qp1 - c)     : -1e30f;
            sacc[nj][3] = (c + 1 <= qp1) ? sacc[nj][3] - slope * (float)(qp1 - c - 1) : -1e30f;
        }

        // ---- online softmax ----
        float mx0 = -1e30f, mx1 = -1e30f;
#pragma unroll
        for (int nj = 0; nj < 8; nj++) {
            mx0 = fmaxf(mx0, fmaxf(sacc[nj][0], sacc[nj][1]));
            mx1 = fmaxf(mx1, fmaxf(sacc[nj][2], sacc[nj][3]));
        }
        mx0 = fmaxf(mx0, __shfl_xor_sync(0xffffffffu, mx0, 1));
        mx0 = fmaxf(mx0, __shfl_xor_sync(0xffffffffu, mx0, 2));
        mx1 = fmaxf(mx1, __shfl_xor_sync(0xffffffffu, mx1, 1));
        mx1 = fmaxf(mx1, __shfl_xor_sync(0xffffffffu, mx1, 2));
        float mn0 = fmaxf(m0r, mx0), mn1 = fmaxf(m1r, mx1);
        float corr0 = __expf(m0r - mn0), corr1 = __expf(m1r - mn1);
        m0r = mn0; m1r = mn1;

        float ls0 = 0.f, ls1 = 0.f;
#pragma unroll
        for (int nj = 0; nj < 8; nj++) {
            sacc[nj][0] = __expf(sacc[nj][0] - mn0);
            sacc[nj][1] = __expf(sacc[nj][1] - mn0);
            sacc[nj][2] = __expf(sacc[nj][2] - mn1);
            sacc[nj][3] = __expf(sacc[nj][3] - mn1);
            ls0 += sacc[nj][0] + sacc[nj][1];
            ls1 += sacc[nj][2] + sacc[nj][3];
        }
        ls0 += __shfl_xor_sync(0xffffffffu, ls0, 1);
        ls0 += __shfl_xor_sync(0xffffffffu, ls0, 2);
        ls1 += __shfl_xor_sync(0xffffffffu, ls1, 1);
        ls1 += __shfl_xor_sync(0xffffffffu, ls1, 2);
        l0r = l0r * corr0 + ls0;
        l1r = l1r * corr1 + ls1;

#pragma unroll
        for (int e = 0; e < 16; e++) {
            Oacc[e][0] *= corr0; Oacc[e][1] *= corr0;
            Oacc[e][2] *= corr1; Oacc[e][3] *= corr1;
        }

        // ---- P -> fp16 A-fragments (4 k16 tiles) ----
        uint32_t phi[4][4];
#pragma unroll
        for (int t = 0; t < 4; t++) {
            phi[t][0] = pack_f2h2(sacc[2 * t][0], sacc[2 * t][1]);
            phi[t][1] = pack_f2h2(sacc[2 * t][2], sacc[2 * t][3]);
            phi[t][2] = pack_f2h2(sacc[2 * t + 1][0], sacc[2 * t + 1][1]);
            phi[t][3] = pack_f2h2(sacc[2 * t + 1][2], sacc[2 * t + 1][3]);
        }

        // ---- O += P V ----
#pragma unroll
        for (int t = 0; t < 4; t++) {
#pragma unroll
            for (int u = 0; u < 8; u++) {
                uint32_t th[4];
                ldm_x4_t(th, sVh + aswz(t * 16 + fr, 2 * u + fs));
                mma_f16(Oacc[2 * u], phi[t], th[0], th[1]);
                mma_f16(Oacc[2 * u + 1], phi[t], th[2], th[3]);
            }
        }
        __syncthreads();
        if (kt + 2 <= kt_end) load_kv(kt + 2);
        else asm volatile("cp.async.commit_group;" ::: "memory");
    }

    // ---- epilogue: normalize + fp16 output ----
    float inv0 = 1.f / l0r, inv1 = 1.f / l1r;
    size_t row0g = (size_t)(b * S_ + row0);
#pragma unroll
    for (int e = 0; e < 16; e++) {
        int colb = h * 128 + e * 8 + (lane & 3) * 2;
        uint32_t hp0 = pack_f2h2(Oacc[e][0] * inv0, Oacc[e][1] * inv0);
        uint32_t hp1 = pack_f2h2(Oacc[e][2] * inv1, Oacc[e][3] * inv1);
        *(uint32_t*)&Ohi[row0g * 2048 + colb] = hp0;
        *(uint32_t*)&Ohi[(row0g + 8) * 2048 + colb] = hp1;
    }
}

// ---------------------------------------------------------------------------
extern "C" void kernel_launch(void* const* d_in, const int* in_sizes, int n_in,
                              void* d_out, int out_size)
{
    const float* residual = (const float*)d_in[0];
    const float* W_Q = (const float*)d_in[1];
    const float* W_K = (const float*)d_in[2];
    const float* W_V = (const float*)d_in[3];
    const float* W_O = (const float*)d_in[4];
    const int* sp = (const int*)d_in[5];

    float* out = (float*)d_out;
    float* k_cache = out + (size_t)B_ * S_ * D_;
    float* v_cache = k_cache + (size_t)B_ * S_ * KVH_ * DH_;

    float* qkv_ptr;
    __half *Ahi, *Whi, *WOhi, *Phi, *Khi, *Vhi;
    cudaGetSymbolAddress((void**)&qkv_ptr, g_qkv);
    cudaGetSymbolAddress((void**)&Ahi, g_Ahi);
    cudaGetSymbolAddress((void**)&Whi, g_Whi);
    cudaGetSymbolAddress((void**)&WOhi, g_WOhi);
    cudaGetSymbolAddress((void**)&Phi, g_Phi);
    cudaGetSymbolAddress((void**)&Khi, g_Khi);
    cudaGetSymbolAddress((void**)&Vhi, g_Vhi);

    cudaFuncSetAttribute(hmma_gemm, cudaFuncAttributeMaxDynamicSharedMemorySize,
                         GEMM_SMEM);
    cudaFuncSetAttribute(attn_mma_kernel, cudaFuncAttributeMaxDynamicSharedMemorySize,
                         ATT2_SMEM);

    // 0) converts
    cvt_kernel<<<(M_ * D_ / 4 + 255) / 256, 256>>>(residual, Ahi, M_ * D_ / 4);
    cvt_kernel<<<(2048 * 2048 / 4 + 255) / 256, 256>>>(W_Q, Whi, 2048 * 2048 / 4);
    cvt_kernel<<<(512 * 2048 / 4 + 255) / 256, 256>>>(
        W_K, Whi + (size_t)2048 * 2048, 512 * 2048 / 4);
    cvt_kernel<<<(512 * 2048 / 4 + 255) / 256, 256>>>(
        W_V, Whi + (size_t)2560 * 2048, 512 * 2048 / 4);
    transpose_cvt_wo<<<dim3(64, 64), 256>>>(W_O, WOhi);

    // 1) fused QKV projection (fp16 single-pass)
    hmma_gemm<<<dim3(NQKV / 128, M_ / 128), 256, GEMM_SMEM>>>(
        Ahi, Whi, qkv_ptr, NQKV);

    // 2) RoPE producer (Qhi reuses g_Ahi)
    rope_split_kernel<<<M_, 256>>>(qkv_ptr, k_cache, v_cache,
                                   Ahi, Khi, Vhi, sp);

    // 3) tensor-core attention (fp16) -> fp16 output
    attn_mma_kernel<<<dim3(S_ / 64, B_ * H_), 128, ATT2_SMEM>>>(
        Ahi, Khi, Vhi, Phi, sp);

    // 4) output projection (fp16 single-pass)
    hmma_gemm<<<dim3(D_ / 128, M_ / 128), 256, GEMM_SMEM>>>(
        Phi, WOhi, out, D_);
}